// round 12
// baseline (speedup 1.0000x reference)
#include <cuda_runtime.h>
#include <cuda_fp16.h>
#include <math.h>
#include <stdint.h>

#define BB   4
#define CC   1024
#define DD   1024
#define HH   16
#define CD   (CC*DD)          // 1048576
#define BCD  (BB*CD)          // 4194304
#define H1SZ (BB*4096*1024)   // 16777216

// ---------------- scratch (static __device__ arrays; no runtime alloc) ---------------
__device__ __half g_ln_hi[3*BCD],  g_ln_lo[3*BCD];
__device__ __half g_qkv_hi[3*BCD], g_qkv_lo[3*BCD];
__device__ __half g_w_hi[3*CD];
__device__ __half g_c1w_hi[4*CD];
__device__ __half g_c2w_hi[4*CD];
__device__ __half g_xl_hi[BCD];
__device__ __half g_h1_hi[H1SZ];
__device__ float g_x[BCD];
__device__ float g_bqkv[3*1024];

// =====================================================================================
// helpers
// =====================================================================================
__device__ __forceinline__ uint32_t smem_u32(const void* p) {
    uint32_t a;
    asm("{ .reg .u64 t; cvta.to.shared.u64 t, %1; cvt.u32.u64 %0, t; }" : "=r"(a) : "l"(p));
    return a;
}
__device__ __forceinline__ void cpa16(uint32_t s, const void* g) {
    asm volatile("cp.async.cg.shared.global [%0], [%1], 16;" :: "r"(s), "l"(g));
}
__device__ __forceinline__ void ldsm4(uint32_t addr, uint32_t& r0, uint32_t& r1,
                                      uint32_t& r2, uint32_t& r3) {
    asm volatile("ldmatrix.sync.aligned.m8n8.x4.shared.b16 {%0,%1,%2,%3}, [%4];"
                 : "=r"(r0), "=r"(r1), "=r"(r2), "=r"(r3) : "r"(addr));
}
__device__ __forceinline__ void ldsm4t(uint32_t addr, uint32_t& r0, uint32_t& r1,
                                       uint32_t& r2, uint32_t& r3) {
    asm volatile("ldmatrix.sync.aligned.m8n8.x4.trans.shared.b16 {%0,%1,%2,%3}, [%4];"
                 : "=r"(r0), "=r"(r1), "=r"(r2), "=r"(r3) : "r"(addr));
}
__device__ __forceinline__ void mma16816(float* c, const uint32_t* a, const uint32_t* b) {
    asm volatile(
        "mma.sync.aligned.m16n8k16.row.col.f32.f16.f16.f32 "
        "{%0,%1,%2,%3}, {%4,%5,%6,%7}, {%8,%9}, {%0,%1,%2,%3};"
        : "+f"(c[0]), "+f"(c[1]), "+f"(c[2]), "+f"(c[3])
        : "r"(a[0]), "r"(a[1]), "r"(a[2]), "r"(a[3]), "r"(b[0]), "r"(b[1]));
}
__device__ __forceinline__ void split1(float v, __half& h, __half& l) {
    h = __float2half_rn(v);
    l = __float2half_rn(v - __half2float(h));
}

// =====================================================================================
// Tensor-core GEMM (R11 shell, unchanged): block 128x64, 4 warps, BK=32,
// 2-stage cp.async race-free, 3 CTAs/SM.
// =====================================================================================
template<int NMMA, int OMODE, bool BTRANS, bool ACONV, bool BIAS_M, bool BIAS_N,
         bool GELUF, bool ADDF, bool SCALEF>
__global__ void __launch_bounds__(128, 3)
tc2_gemm(const void* Ahv, const __half* Alo, long strideA, int lda,
         const __half* Bhi, const __half* Blo,
         int bDiv, long bHi, long bLo, int ldb,
         float* Cf, __half* Chi, __half* Clo,
         int cDiv, long cHi, long cLo, int ldc,
         const float* Add, const float* bias, int biasZ,
         float alpha, int M, int N, int K)
{
    constexpr int BN  = 64;
    constexpr int BK  = 32;
    constexpr int SKA = 40;
    constexpr int SN  = BN + 8;
    constexpr int ASZ = 128 * SKA;
    constexpr int BSZ = BTRANS ? (BK * SN) : (BN * SKA);
    constexpr int APL = (NMMA >= 2) ? 2 : 1;
    constexpr int BPL = (NMMA == 3) ? 2 : 1;
    constexpr int STAGE = APL * ASZ + BPL * BSZ;
    constexpr int MF = 4;
    constexpr int NF = 4;

    extern __shared__ __half sm[];

    const int tid = threadIdx.x, wid = tid >> 5, lid = tid & 31;
    const int wm = wid >> 1, wn = wid & 1;
    const int z = blockIdx.z;
    const int row0 = blockIdx.y * 128, col0 = blockIdx.x * BN;

    const __half* Ahi = ACONV ? nullptr : ((const __half*)Ahv + (long)z * strideA);
    const __half* Alz = (ACONV || APL == 1) ? nullptr : (Alo + (long)z * strideA);
    const float* Af = ACONV ? ((const float*)Ahv + (long)z * strideA) : nullptr;
    Bhi += (long)(z / bDiv) * bHi + (long)(z % bDiv) * bLo;
    if (NMMA == 3) Blo += (long)(z / bDiv) * bHi + (long)(z % bDiv) * bLo;
    const long coff = (long)(z / cDiv) * cHi + (long)(z % cDiv) * cLo;
    if (BIAS_N || BIAS_M) bias += (long)z * biasZ;

    const uint32_t smBase = smem_u32(sm);
    const int nIt = K / BK;

    float acc[MF][NF][4];
#pragma unroll
    for (int i = 0; i < MF; i++)
#pragma unroll
        for (int j = 0; j < NF; j++)
#pragma unroll
            for (int r = 0; r < 4; r++) acc[i][j][r] = 0.f;

    float4 av[8];

    auto issueTile = [&](int it, int st) {
        const int k0 = it * BK;
        const uint32_t sbase = smBase + (uint32_t)(st * STAGE) * 2;
        if (!ACONV) {
#pragma unroll
            for (int pl = 0; pl < APL; pl++) {
                const __half* Ag = pl ? Alz : Ahi;
                const uint32_t sd = sbase + (uint32_t)(pl * ASZ) * 2;
#pragma unroll
                for (int i = 0; i < 4; i++) {
                    int idx = tid + (i << 7);
                    int r = idx >> 2, c8 = (idx & 3) << 3;
                    cpa16(sd + (uint32_t)(r * SKA + c8) * 2,
                          Ag + (long)(row0 + r) * lda + k0 + c8);
                }
            }
        }
        if (BTRANS) {
#pragma unroll
            for (int pl = 0; pl < BPL; pl++) {
                const __half* Bg = pl ? Blo : Bhi;
                const uint32_t sd = sbase + (uint32_t)(APL * ASZ + pl * BSZ) * 2;
#pragma unroll
                for (int i = 0; i < 2; i++) {
                    int idx = tid + (i << 7);
                    int k = idx >> 3, c8 = (idx & 7) << 3;
                    cpa16(sd + (uint32_t)(k * SN + c8) * 2,
                          Bg + (long)(k0 + k) * ldb + col0 + c8);
                }
            }
        } else {
#pragma unroll
            for (int pl = 0; pl < BPL; pl++) {
                const __half* Bg = pl ? Blo : Bhi;
                const uint32_t sd = sbase + (uint32_t)(APL * ASZ + pl * BSZ) * 2;
#pragma unroll
                for (int i = 0; i < 2; i++) {
                    int idx = tid + (i << 7);
                    int r = idx >> 2, c8 = (idx & 3) << 3;
                    cpa16(sd + (uint32_t)(r * SKA + c8) * 2,
                          Bg + (long)(col0 + r) * ldb + k0 + c8);
                }
            }
        }
    };
    auto ldgA = [&](int it) {
        const int k0 = it * BK;
#pragma unroll
        for (int i = 0; i < 8; i++) {
            int idx = tid + (i << 7);
            int r = idx >> 3, c4 = (idx & 7) << 2;
            av[i] = *(const float4*)(Af + (long)(row0 + r) * lda + k0 + c4);
        }
    };
    auto stsA = [&](int st) {
        __half* sAhi = sm + st * STAGE;
        __half* sAlo = sAhi + ASZ;
#pragma unroll
        for (int i = 0; i < 8; i++) {
            int idx = tid + (i << 7);
            int r = idx >> 3, c4 = (idx & 7) << 2;
            if (APL == 2) {
                __half h[4], l[4];
                split1(av[i].x, h[0], l[0]); split1(av[i].y, h[1], l[1]);
                split1(av[i].z, h[2], l[2]); split1(av[i].w, h[3], l[3]);
                *(uint2*)(sAhi + r * SKA + c4) = *(uint2*)h;
                *(uint2*)(sAlo + r * SKA + c4) = *(uint2*)l;
            } else {
                __half h[4] = {__float2half_rn(av[i].x), __float2half_rn(av[i].y),
                               __float2half_rn(av[i].z), __float2half_rn(av[i].w)};
                *(uint2*)(sAhi + r * SKA + c4) = *(uint2*)h;
            }
        }
    };

    if (ACONV) { ldgA(0); stsA(0); }
    issueTile(0, 0);
    asm volatile("cp.async.commit_group;");

    for (int it = 0; it < nIt; it++) {
        const int s = it & 1;
        asm volatile("cp.async.wait_group 0;");
        __syncthreads();
        if (it + 1 < nIt) {
            if (ACONV) ldgA(it + 1);
            issueTile(it + 1, s ^ 1);
            asm volatile("cp.async.commit_group;");
        }

        const uint32_t base = smBase + (uint32_t)(s * STAGE) * 2;
        const uint32_t aHiB = base, aLoB = base + ASZ * 2;
        const uint32_t bHiB = base + APL * ASZ * 2, bLoB = bHiB + BSZ * 2;

#pragma unroll
        for (int ks = 0; ks < 2; ks++) {
            uint32_t ah[MF][4], al[MF][4], bh[NF][2], bl[NF][2];
#pragma unroll
            for (int mf = 0; mf < MF; mf++) {
                uint32_t off = (uint32_t)((wm * 64 + mf * 16 + (lid & 15)) * SKA
                                          + ks * 16 + (lid >> 4) * 8) * 2;
                ldsm4(aHiB + off, ah[mf][0], ah[mf][1], ah[mf][2], ah[mf][3]);
                if (APL == 2)
                    ldsm4(aLoB + off, al[mf][0], al[mf][1], al[mf][2], al[mf][3]);
            }
            if (BTRANS) {
#pragma unroll
                for (int p = 0; p < NF / 2; p++) {
                    uint32_t off = (uint32_t)((ks * 16 + (lid & 15)) * SN
                                              + wn * 32 + p * 16 + (lid >> 4) * 8) * 2;
                    ldsm4t(bHiB + off, bh[2*p][0], bh[2*p][1], bh[2*p+1][0], bh[2*p+1][1]);
                    if (NMMA == 3)
                        ldsm4t(bLoB + off, bl[2*p][0], bl[2*p][1], bl[2*p+1][0], bl[2*p+1][1]);
                }
            } else {
#pragma unroll
                for (int p = 0; p < NF / 2; p++) {
                    uint32_t off = (uint32_t)((wn * 32 + p * 16 + (lid & 7) + (lid >> 4) * 8) * SKA
                                              + ks * 16 + ((lid >> 3) & 1) * 8) * 2;
                    ldsm4(bHiB + off, bh[2*p][0], bh[2*p][1], bh[2*p+1][0], bh[2*p+1][1]);
                    if (NMMA == 3)
                        ldsm4(bLoB + off, bl[2*p][0], bl[2*p][1], bl[2*p+1][0], bl[2*p+1][1]);
                }
            }
#pragma unroll
            for (int mf = 0; mf < MF; mf++)
#pragma unroll
                for (int nf = 0; nf < NF; nf++)
                    mma16816(acc[mf][nf], ah[mf], bh[nf]);
            if (NMMA == 3) {
#pragma unroll
                for (int mf = 0; mf < MF; mf++)
#pragma unroll
                    for (int nf = 0; nf < NF; nf++)
                        mma16816(acc[mf][nf], ah[mf], bl[nf]);
            }
            if (NMMA >= 2) {
#pragma unroll
                for (int mf = 0; mf < MF; mf++)
#pragma unroll
                    for (int nf = 0; nf < NF; nf++)
                        mma16816(acc[mf][nf], al[mf], bh[nf]);
            }
        }
        if (ACONV && it + 1 < nIt) stsA(s ^ 1);
    }

    // ---- epilogue ----
    float* Cp = (OMODE == 0) ? (Cf + coff) : nullptr;
    __half* ChP = (OMODE != 0) ? (Chi + coff) : nullptr;
    __half* ClP = (OMODE == 1) ? (Clo + coff) : nullptr;
    const float* Ap2 = ADDF ? (Add + coff) : nullptr;
    const int rBase = row0 + wm * 64 + (lid >> 2);
    const int cBase = col0 + wn * 32 + (lid & 3) * 2;
#pragma unroll
    for (int mf = 0; mf < MF; mf++) {
#pragma unroll
        for (int half = 0; half < 2; half++) {
            const int gr = rBase + mf * 16 + half * 8;
            const float bm = BIAS_M ? bias[gr] : 0.f;
#pragma unroll
            for (int nf = 0; nf < NF; nf++) {
                const int gc = cBase + nf * 8;
                float v0 = acc[mf][nf][half * 2 + 0];
                float v1 = acc[mf][nf][half * 2 + 1];
                if (SCALEF) { v0 *= alpha; v1 *= alpha; }
                if (BIAS_M) { v0 += bm; v1 += bm; }
                if (BIAS_N) { v0 += bias[gc]; v1 += bias[gc + 1]; }
                if (GELUF) {
                    v0 = 0.5f * v0 * (1.0f + erff(v0 * 0.70710678118654752f));
                    v1 = 0.5f * v1 * (1.0f + erff(v1 * 0.70710678118654752f));
                }
                long off = (long)gr * ldc + gc;
                if (ADDF) { v0 += Ap2[off]; v1 += Ap2[off + 1]; }
                if (OMODE == 1) {
                    __half h0, l0, h1, l1;
                    split1(v0, h0, l0); split1(v1, h1, l1);
                    __half hp[2] = {h0, h1}, lp[2] = {l0, l1};
                    *(uint32_t*)(ChP + off) = *(uint32_t*)hp;
                    *(uint32_t*)(ClP + off) = *(uint32_t*)lp;
                } else if (OMODE == 2) {
                    __half hp[2] = {__float2half_rn(v0), __float2half_rn(v1)};
                    *(uint32_t*)(ChP + off) = *(uint32_t*)hp;
                } else {
                    *(float2*)(Cp + off) = make_float2(v0, v1);
                }
            }
        }
    }
}

// =====================================================================================
// FUSED attention: S = 0.125*QK^T, softmax-one -> attn out, then O = P V in-register
// (C-fragment == A-fragment layout trick), 8-way warp reduce, +x1 residual -> g_x.
// grid (32, 64), 256 threads. smem 85248 B (phases overlay each other).
// =====================================================================================
__global__ void __launch_bounds__(256, 1)
attn_fused(const __half* __restrict__ qHi, const __half* __restrict__ qLo,
           const __half* __restrict__ kHi, const __half* __restrict__ kLo,
           const __half* __restrict__ vHi,
           const float* __restrict__ x1, float* __restrict__ xout,
           float* __restrict__ attn)
{
    constexpr int SK = 72;
    constexpr int QPL = 32 * SK;          // 2304
    constexpr int KPL = 128 * SK;         // 9216
    extern __shared__ __half sm[];
    float* redA = (float*)(sm + 2 * QPL + 4 * KPL);   // byte 82944
    float* redB = redA + 32 * 9;

    const int tid = threadIdx.x, wid = tid >> 5, lid = tid & 31;
    const int z = blockIdx.y;
    const int row0 = blockIdx.x * 32;
    const __half* Qh = qHi + (long)z * 65536;
    const __half* Ql = qLo + (long)z * 65536;
    const __half* Kh = kHi + (long)z * 65536;
    const __half* Kl = kLo + (long)z * 65536;
    const __half* Vh = vHi + (long)z * 65536;
    attn += (long)z * 1048576;

    const uint32_t smBase = smem_u32(sm);

    // ================= phase 1: QK^T =================
    {
        int r = tid >> 3, c8 = (tid & 7) << 3;
        cpa16(smBase + (uint32_t)(r * SK + c8) * 2,        Qh + (long)(row0 + r) * 64 + c8);
        cpa16(smBase + (uint32_t)(QPL + r * SK + c8) * 2,  Ql + (long)(row0 + r) * 64 + c8);
    }
    auto issueK = [&](int ch, int st) {
        const uint32_t sb = smBase + (uint32_t)(2 * QPL + st * 2 * KPL) * 2;
#pragma unroll
        for (int pl = 0; pl < 2; pl++) {
            const __half* Kg = pl ? Kl : Kh;
            const uint32_t sd = sb + (uint32_t)(pl * KPL) * 2;
#pragma unroll
            for (int i = 0; i < 4; i++) {
                int idx = tid + (i << 8);
                int r = idx >> 3, c8 = (idx & 7) << 3;
                cpa16(sd + (uint32_t)(r * SK + c8) * 2,
                      Kg + (long)(ch * 128 + r) * 64 + c8);
            }
        }
    };
    issueK(0, 0);
    asm volatile("cp.async.commit_group;");

    float acc[2][8][2][4];
#pragma unroll
    for (int mf = 0; mf < 2; mf++)
#pragma unroll
        for (int ch = 0; ch < 8; ch++)
#pragma unroll
            for (int nf = 0; nf < 2; nf++)
#pragma unroll
                for (int r = 0; r < 4; r++) acc[mf][ch][nf][r] = 0.f;

    uint32_t aH[4][2][4], aL[4][2][4];

    for (int ch = 0; ch < 8; ch++) {
        asm volatile("cp.async.wait_group 0;");
        __syncthreads();
        if (ch + 1 < 8) {
            issueK(ch + 1, (ch + 1) & 1);
            asm volatile("cp.async.commit_group;");
        }
        if (ch == 0) {
#pragma unroll
            for (int ks = 0; ks < 4; ks++)
#pragma unroll
                for (int mf = 0; mf < 2; mf++) {
                    uint32_t off = (uint32_t)((mf * 16 + (lid & 15)) * SK
                                              + ks * 16 + (lid >> 4) * 8) * 2;
                    ldsm4(smBase + off,           aH[ks][mf][0], aH[ks][mf][1],
                                                  aH[ks][mf][2], aH[ks][mf][3]);
                    ldsm4(smBase + QPL * 2 + off, aL[ks][mf][0], aL[ks][mf][1],
                                                  aL[ks][mf][2], aL[ks][mf][3]);
                }
        }
        const int st = ch & 1;
        const uint32_t kHiB = smBase + (uint32_t)(2 * QPL + st * 2 * KPL) * 2;
        const uint32_t kLoB = kHiB + (uint32_t)KPL * 2;
#pragma unroll
        for (int ks = 0; ks < 4; ks++) {
            uint32_t bh[2][2], bl[2][2];
            uint32_t off = (uint32_t)((wid * 16 + (lid & 7) + (lid >> 4) * 8) * SK
                                      + ks * 16 + ((lid >> 3) & 1) * 8) * 2;
            ldsm4(kHiB + off, bh[0][0], bh[0][1], bh[1][0], bh[1][1]);
            ldsm4(kLoB + off, bl[0][0], bl[0][1], bl[1][0], bl[1][1]);
#pragma unroll
            for (int mf = 0; mf < 2; mf++)
#pragma unroll
                for (int nf = 0; nf < 2; nf++) {
                    mma16816(acc[mf][ch][nf], aH[ks][mf], bh[nf]);
                    mma16816(acc[mf][ch][nf], aH[ks][mf], bl[nf]);
                    mma16816(acc[mf][ch][nf], aL[ks][mf], bh[nf]);
                }
        }
    }

    // ================= phase 2: softmax-one =================
    const int rq = lid >> 2, cq = lid & 3;
#pragma unroll
    for (int mf = 0; mf < 2; mf++)
#pragma unroll
        for (int ch = 0; ch < 8; ch++)
#pragma unroll
            for (int nf = 0; nf < 2; nf++)
#pragma unroll
                for (int r = 0; r < 4; r++) acc[mf][ch][nf][r] *= 0.125f;

    float mx[2][2];
#pragma unroll
    for (int mf = 0; mf < 2; mf++)
#pragma unroll
        for (int half = 0; half < 2; half++) {
            float m = -1e30f;
#pragma unroll
            for (int ch = 0; ch < 8; ch++)
#pragma unroll
                for (int nf = 0; nf < 2; nf++)
                    m = fmaxf(m, fmaxf(acc[mf][ch][nf][half*2], acc[mf][ch][nf][half*2+1]));
            m = fmaxf(m, __shfl_xor_sync(0xffffffffu, m, 1));
            m = fmaxf(m, __shfl_xor_sync(0xffffffffu, m, 2));
            mx[mf][half] = m;
        }
    if (cq == 0) {
#pragma unroll
        for (int mf = 0; mf < 2; mf++)
#pragma unroll
            for (int half = 0; half < 2; half++)
                redA[(mf * 16 + half * 8 + rq) * 9 + wid] = mx[mf][half];
    }
    __syncthreads();
#pragma unroll
    for (int mf = 0; mf < 2; mf++)
#pragma unroll
        for (int half = 0; half < 2; half++) {
            float m = -1e30f;
            const float* rr = redA + (mf * 16 + half * 8 + rq) * 9;
#pragma unroll
            for (int w = 0; w < 8; w++) m = fmaxf(m, rr[w]);
            mx[mf][half] = m;
        }

    float sum[2][2] = {{0.f, 0.f}, {0.f, 0.f}};
#pragma unroll
    for (int mf = 0; mf < 2; mf++)
#pragma unroll
        for (int half = 0; half < 2; half++) {
            const float m = mx[mf][half];
            float s = 0.f;
#pragma unroll
            for (int ch = 0; ch < 8; ch++)
#pragma unroll
                for (int nf = 0; nf < 2; nf++) {
                    float e0 = __expf(acc[mf][ch][nf][half*2]     - m);
                    float e1 = __expf(acc[mf][ch][nf][half*2 + 1] - m);
                    acc[mf][ch][nf][half*2]     = e0;
                    acc[mf][ch][nf][half*2 + 1] = e1;
                    s += e0 + e1;
                }
            s += __shfl_xor_sync(0xffffffffu, s, 1);
            s += __shfl_xor_sync(0xffffffffu, s, 2);
            sum[mf][half] = s;
        }
    if (cq == 0) {
#pragma unroll
        for (int mf = 0; mf < 2; mf++)
#pragma unroll
            for (int half = 0; half < 2; half++)
                redB[(mf * 16 + half * 8 + rq) * 9 + wid] = sum[mf][half];
    }
    __syncthreads();
#pragma unroll
    for (int mf = 0; mf < 2; mf++)
#pragma unroll
        for (int half = 0; half < 2; half++) {
            float s = 0.f;
            const float* rr = redB + (mf * 16 + half * 8 + rq) * 9;
#pragma unroll
            for (int w = 0; w < 8; w++) s += rr[w];
            sum[mf][half] = 1.0f / (1.0f + s);
        }

    // attn output writes (normalized P)
#pragma unroll
    for (int mf = 0; mf < 2; mf++)
#pragma unroll
        for (int half = 0; half < 2; half++) {
            const int gr = row0 + mf * 16 + half * 8 + rq;
            const float inv = sum[mf][half];
#pragma unroll
            for (int ch = 0; ch < 8; ch++)
#pragma unroll
                for (int nf = 0; nf < 2; nf++) {
                    const int gc = ch * 128 + wid * 16 + nf * 8 + cq * 2;
                    *(float2*)(attn + (long)gr * 1024 + gc) =
                        make_float2(acc[mf][ch][nf][half*2] * inv,
                                    acc[mf][ch][nf][half*2+1] * inv);
                }
        }

    // ================= phase 3: P -> fp16 A-fragments (in registers) =================
    // 16x16 P tile (mf, ch) = C-frags of nf=0,1. A-frag reg order: [nf0 c0c1][nf0 c2c3]
    // [nf1 c0c1][nf1 c2c3]; c0c1 scaled by inv[mf][0] (rows g), c2c3 by inv[mf][1] (g+8).
    uint32_t pk[2][8][4];
#pragma unroll
    for (int mf = 0; mf < 2; mf++)
#pragma unroll
        for (int ch = 0; ch < 8; ch++)
#pragma unroll
            for (int nf = 0; nf < 2; nf++) {
                __half2 h0 = __floats2half2_rn(acc[mf][ch][nf][0] * sum[mf][0],
                                               acc[mf][ch][nf][1] * sum[mf][0]);
                __half2 h1 = __floats2half2_rn(acc[mf][ch][nf][2] * sum[mf][1],
                                               acc[mf][ch][nf][3] * sum[mf][1]);
                pk[mf][ch][nf * 2 + 0] = *(uint32_t*)&h0;
                pk[mf][ch][nf * 2 + 1] = *(uint32_t*)&h1;
            }

    // ================= phase 4: O = P V (V ring reuses dead Q/K smem) =================
    constexpr int SV = 72;
    constexpr int VPL = 128 * SV;         // 9216 halves per stage
    __syncthreads();                      // all K/Q smem reads retired

    auto issueV = [&](int ch, int st) {
        const uint32_t sd = smBase + (uint32_t)(st * VPL) * 2;
#pragma unroll
        for (int i = 0; i < 4; i++) {
            int idx = tid + (i << 8);
            int r = idx >> 3, c8 = (idx & 7) << 3;
            cpa16(sd + (uint32_t)(r * SV + c8) * 2,
                  Vh + (long)(ch * 128 + r) * 64 + c8);
        }
    };
    issueV(0, 0);
    asm volatile("cp.async.commit_group;");

    float oacc[2][8][4];
#pragma unroll
    for (int mf = 0; mf < 2; mf++)
#pragma unroll
        for (int nb = 0; nb < 8; nb++)
#pragma unroll
            for (int r = 0; r < 4; r++) oacc[mf][nb][r] = 0.f;

    for (int ch = 0; ch < 8; ch++) {
        asm volatile("cp.async.wait_group 0;");
        __syncthreads();
        if (ch + 1 < 8) {
            issueV(ch + 1, (ch + 1) & 1);
            asm volatile("cp.async.commit_group;");
        }
        const uint32_t vB = smBase + (uint32_t)((ch & 1) * VPL) * 2;
        uint32_t bv[8][2];
#pragma unroll
        for (int p = 0; p < 4; p++) {
            uint32_t off = (uint32_t)((wid * 16 + (lid & 15)) * SV
                                      + p * 16 + (lid >> 4) * 8) * 2;
            ldsm4t(vB + off, bv[2*p][0], bv[2*p][1], bv[2*p+1][0], bv[2*p+1][1]);
        }
#pragma unroll
        for (int mf = 0; mf < 2; mf++)
#pragma unroll
            for (int nb = 0; nb < 8; nb++)
                mma16816(oacc[mf][nb], pk[mf][ch], bv[nb]);
    }

    // ================= phase 5: cross-warp reduce + residual + scatter =================
    __syncthreads();                      // all V smem reads retired
    float* Ored = (float*)sm;             // overlay: [8][32][64] f32 = 64 KB
#pragma unroll
    for (int mf = 0; mf < 2; mf++)
#pragma unroll
        for (int half = 0; half < 2; half++) {
            const int rl = mf * 16 + half * 8 + rq;
#pragma unroll
            for (int nb = 0; nb < 8; nb++) {
                const int c = nb * 8 + cq * 2;
                *(float2*)(Ored + ((wid * 32 + rl) * 64 + c)) =
                    make_float2(oacc[mf][nb][half*2], oacc[mf][nb][half*2+1]);
            }
        }
    __syncthreads();

    // thread handles row rl2 = tid>>3 (32 rows), cols (tid&7)*8 .. +7
    {
        const int rl2 = tid >> 3, c0 = (tid & 7) << 3;
        const long gbase = (long)(z >> 4) * CD + (long)(z & 15) * 64
                         + (long)(row0 + rl2) * 1024 + c0;
        float o[8];
#pragma unroll
        for (int j = 0; j < 8; j++) o[j] = x1[gbase + j];
#pragma unroll
        for (int w = 0; w < 8; w++) {
            const float* src = Ored + ((w * 32 + rl2) * 64 + c0);
#pragma unroll
            for (int j = 0; j < 8; j++) o[j] += src[j];
        }
        *(float4*)(xout + gbase)     = make_float4(o[0], o[1], o[2], o[3]);
        *(float4*)(xout + gbase + 4) = make_float4(o[4], o[5], o[6], o[7]);
    }
}

// =====================================================================================
__global__ void cvt_hi(const float* __restrict__ s, __half* __restrict__ hi, int n4)
{
    int i = blockIdx.x * 256 + threadIdx.x;
    if (i >= n4) return;
    float4 v = ((const float4*)s)[i];
    __half h[4] = {__float2half_rn(v.x), __float2half_rn(v.y),
                   __float2half_rn(v.z), __float2half_rn(v.w)};
    ((uint2*)hi)[i] = *(uint2*)h;
}

__global__ void bias_gather(const float* a, const float* b, const float* c, float* o)
{
    const float* src[3] = {a, b, c};
    o[blockIdx.x * 1024 + threadIdx.x] = src[blockIdx.x][threadIdx.x];
}

// =====================================================================================
__global__ void ln3_kernel(const float* __restrict__ x, int nOut,
    const float* __restrict__ w0, const float* __restrict__ b0,
    const float* __restrict__ w1, const float* __restrict__ b1,
    const float* __restrict__ w2, const float* __restrict__ b2,
    __half* __restrict__ oHi, __half* __restrict__ oLo)
{
    const int dx   = threadIdx.x & 31;
    const int lane = threadIdx.x >> 5;
    const int d    = blockIdx.x * 32 + dx;
    const long base = (long)blockIdx.y * CD + d;

    float s = 0.f, ss = 0.f;
    for (int c = lane; c < CC; c += 8) {
        float v = x[base + (long)c * DD];
        s += v; ss += v * v;
    }
    __shared__ float sS[8][33], sQ[8][33];
    sS[lane][dx] = s; sQ[lane][dx] = ss;
    __syncthreads();
    if (lane == 0) {
        float ts = 0.f, tq = 0.f;
        #pragma unroll
        for (int i = 0; i < 8; i++) { ts += sS[i][dx]; tq += sQ[i][dx]; }
        float mean = ts * (1.0f / CC);
        float var  = tq * (1.0f / CC) - mean * mean;
        sS[0][dx] = mean;
        sQ[0][dx] = rsqrtf(var + 1e-6f);
    }
    __syncthreads();
    const float mean = sS[0][dx];
    const float rstd = sQ[0][dx];
    const float* W[3] = {w0, w1, w2};
    const float* Bv[3] = {b0, b1, b2};
    for (int c = lane; c < CC; c += 8) {
        long idx = base + (long)c * DD;
        float xn = (x[idx] - mean) * rstd;
        for (int p = 0; p < nOut; p++) {
            float v = W[p][c] * xn + Bv[p][c];
            if (oLo) {
                __half h, l;
                split1(v, h, l);
                oHi[(long)p * BCD + idx] = h;
                oLo[(long)p * BCD + idx] = l;
            } else {
                oHi[(long)p * BCD + idx] = __float2half_rn(v);
            }
        }
    }
}

// =====================================================================================
extern "C" void kernel_launch(void* const* d_in, const int* in_sizes, int n_in,
                              void* d_out, int out_size)
{
    const float* x1      = (const float*)d_in[0];
    const float* lnq_w   = (const float*)d_in[1];
    const float* lnq_b   = (const float*)d_in[2];
    const float* lnk_w   = (const float*)d_in[3];
    const float* lnk_b   = (const float*)d_in[4];
    const float* lnv_w   = (const float*)d_in[5];
    const float* lnv_b   = (const float*)d_in[6];
    const float* wq      = (const float*)d_in[7];
    const float* bq      = (const float*)d_in[8];
    const float* wk      = (const float*)d_in[9];
    const float* bk      = (const float*)d_in[10];
    const float* wv      = (const float*)d_in[11];
    const float* bv      = (const float*)d_in[12];
    const float* ffnln_w = (const float*)d_in[13];
    const float* ffnln_b = (const float*)d_in[14];
    const float* conv1_w = (const float*)d_in[15];
    const float* conv1_b = (const float*)d_in[16];
    const float* conv2_w = (const float*)d_in[17];
    const float* conv2_b = (const float*)d_in[18];

    __half *lnHi, *lnLo, *qkvHi, *qkvLo, *wHi;
    __half *c1wHi, *c2wHi, *xlHi, *h1Hi;
    float *xb, *bqkv;
    cudaGetSymbolAddress((void**)&lnHi,  g_ln_hi);   cudaGetSymbolAddress((void**)&lnLo,  g_ln_lo);
    cudaGetSymbolAddress((void**)&qkvHi, g_qkv_hi);  cudaGetSymbolAddress((void**)&qkvLo, g_qkv_lo);
    cudaGetSymbolAddress((void**)&wHi,   g_w_hi);
    cudaGetSymbolAddress((void**)&c1wHi, g_c1w_hi);
    cudaGetSymbolAddress((void**)&c2wHi, g_c2w_hi);
    cudaGetSymbolAddress((void**)&xlHi,  g_xl_hi);
    cudaGetSymbolAddress((void**)&h1Hi,  g_h1_hi);
    cudaGetSymbolAddress((void**)&xb,    g_x);
    cudaGetSymbolAddress((void**)&bqkv,  g_bqkv);

    float* outx = (float*)d_out;
    float* attn = outx + (long)BCD;

    auto kQKV = tc2_gemm<2, 1, false, false, false, true,  false, false, false>;
    auto kC1  = tc2_gemm<1, 2, true,  false, true,  false, true,  false, false>;
    auto kC2  = tc2_gemm<1, 0, true,  false, true,  false, false, true,  false>;
    const int SM_KB  = 2 * (2 * 128 * 40 + 1 * 64 * 40) * 2;  // 51200 (QKV)
    const int SM_1TR = 2 * (1 * 128 * 40 + 1 * 32 * 72) * 2;  // 29696 (C1/C2)
    const int SM_QS = (2 * 32 * 72 + 4 * 128 * 72) * 2 + 2 * 32 * 9 * 4;  // 85248
    cudaFuncSetAttribute(kQKV, cudaFuncAttributeMaxDynamicSharedMemorySize, SM_KB);
    cudaFuncSetAttribute(kC1,  cudaFuncAttributeMaxDynamicSharedMemorySize, SM_1TR);
    cudaFuncSetAttribute(kC2,  cudaFuncAttributeMaxDynamicSharedMemorySize, SM_1TR);
    cudaFuncSetAttribute(attn_fused, cudaFuncAttributeMaxDynamicSharedMemorySize, SM_QS);

    // 0) weight converts + bias gather
    cvt_hi<<<CD / 4 / 256, 256>>>(wq, wHi,          CD / 4);
    cvt_hi<<<CD / 4 / 256, 256>>>(wk, wHi + CD,     CD / 4);
    cvt_hi<<<CD / 4 / 256, 256>>>(wv, wHi + 2 * CD, CD / 4);
    cvt_hi<<<4 * CD / 4 / 256, 256>>>(conv1_w, c1wHi, 4 * CD / 4);
    cvt_hi<<<4 * CD / 4 / 256, 256>>>(conv2_w, c2wHi, 4 * CD / 4);
    bias_gather<<<3, 1024>>>(bq, bk, bv, bqkv);

    // 1) QKV LayerNorms -> hi/lo planes
    dim3 lng(DD / 32, BB);
    ln3_kernel<<<lng, 256>>>(x1, 3, lnq_w, lnq_b, lnk_w, lnk_b, lnv_w, lnv_b, lnHi, lnLo);

    // 2) fused QKV linears (z = 0/1/2), 2-MMA, outputs hi/lo
    dim3 gqkv(16, 32, 3);
    kQKV<<<gqkv, 128, SM_KB>>>(lnHi, lnLo, BCD, 1024, wHi, nullptr, 1, CD, 0, 1024,
                               nullptr, qkvHi, qkvLo, 1, BCD, 0, 1024,
                               nullptr, bqkv, 1024, 1.f, 4096, 1024, 1024);

    // 3+4+5) fused attention: softmax-one probs -> attn out; O + x1 -> g_x
    dim3 gqs(32, BB * HH);
    attn_fused<<<gqs, 256, SM_QS>>>(qkvHi, qkvLo, qkvHi + BCD, qkvLo + BCD,
                                    qkvHi + 2 * (long)BCD, x1, xb, attn);

    // 6) FFN LayerNorm -> xl single plane
    ln3_kernel<<<lng, 256>>>(xb, 1, ffnln_w, ffnln_b, nullptr, nullptr, nullptr, nullptr,
                             xlHi, nullptr);

    // 7) conv1: h1 = GELU(W1 @ xl_z + b1) (1-MMA, single fp16 out)
    dim3 gc1(16, 32, BB);
    kC1<<<gc1, 128, SM_1TR>>>(c1wHi, nullptr, 0, 1024, xlHi, nullptr, 1, CD, 0, 1024,
                              nullptr, h1Hi, nullptr, 1, (long)4096 * 1024, 0, 1024,
                              nullptr, conv1_b, 0, 1.f, 4096, 1024, 1024);

    // 8) conv2 + residual: out = x + (W2 @ h1_z + b2) (1-MMA)
    dim3 gc2(16, 8, BB);
    kC2<<<gc2, 128, SM_1TR>>>(c2wHi, nullptr, 0, 4096, h1Hi, nullptr, 1, (long)4096 * 1024, 0, 1024,
                              outx, nullptr, nullptr, 1, CD, 0, 1024,
                              xb, conv2_b, 0, 1.f, 1024, 1024, 4096);
}

// round 13
// speedup vs baseline: 1.0477x; 1.0477x over previous
#include <cuda_runtime.h>
#include <cuda_fp16.h>
#include <math.h>
#include <stdint.h>

#define BB   4
#define CC   1024
#define DD   1024
#define HH   16
#define CD   (CC*DD)          // 1048576
#define BCD  (BB*CD)          // 4194304
#define H1SZ (BB*4096*1024)   // 16777216

// ---------------- scratch (static __device__ arrays; no runtime alloc) ---------------
__device__ __half g_ln_hi[3*BCD],  g_ln_lo[3*BCD];
__device__ __half g_qkv_hi[3*BCD];                 // q/k/v single fp16 planes
__device__ __half g_w_hi[3*CD];
__device__ __half g_c1w_hi[4*CD];
__device__ __half g_c2w_hi[4*CD];
__device__ __half g_xl_hi[BCD];
__device__ __half g_h1_hi[H1SZ];
__device__ float g_x[BCD];
__device__ float g_bqkv[3*1024];

// =====================================================================================
// helpers
// =====================================================================================
__device__ __forceinline__ uint32_t smem_u32(const void* p) {
    uint32_t a;
    asm("{ .reg .u64 t; cvta.to.shared.u64 t, %1; cvt.u32.u64 %0, t; }" : "=r"(a) : "l"(p));
    return a;
}
__device__ __forceinline__ void cpa16(uint32_t s, const void* g) {
    asm volatile("cp.async.cg.shared.global [%0], [%1], 16;" :: "r"(s), "l"(g));
}
__device__ __forceinline__ void ldsm4(uint32_t addr, uint32_t& r0, uint32_t& r1,
                                      uint32_t& r2, uint32_t& r3) {
    asm volatile("ldmatrix.sync.aligned.m8n8.x4.shared.b16 {%0,%1,%2,%3}, [%4];"
                 : "=r"(r0), "=r"(r1), "=r"(r2), "=r"(r3) : "r"(addr));
}
__device__ __forceinline__ void ldsm4t(uint32_t addr, uint32_t& r0, uint32_t& r1,
                                       uint32_t& r2, uint32_t& r3) {
    asm volatile("ldmatrix.sync.aligned.m8n8.x4.trans.shared.b16 {%0,%1,%2,%3}, [%4];"
                 : "=r"(r0), "=r"(r1), "=r"(r2), "=r"(r3) : "r"(addr));
}
__device__ __forceinline__ void mma16816(float* c, const uint32_t* a, const uint32_t* b) {
    asm volatile(
        "mma.sync.aligned.m16n8k16.row.col.f32.f16.f16.f32 "
        "{%0,%1,%2,%3}, {%4,%5,%6,%7}, {%8,%9}, {%0,%1,%2,%3};"
        : "+f"(c[0]), "+f"(c[1]), "+f"(c[2]), "+f"(c[3])
        : "r"(a[0]), "r"(a[1]), "r"(a[2]), "r"(a[3]), "r"(b[0]), "r"(b[1]));
}
__device__ __forceinline__ void split1(float v, __half& h, __half& l) {
    h = __float2half_rn(v);
    l = __float2half_rn(v - __half2float(h));
}

// =====================================================================================
// Tensor-core GEMM (R11 shell): block 128x64, 4 warps, BK=32, 2-stage cp.async
// race-free, 3 CTAs/SM.
//   NMMA=1: D = a*b ; NMMA=2: D = (a_hi+a_lo)*b ; NMMA=3: + a_hi*b_lo
//   OMODE: 0 = fp32, 1 = fp16 hi/lo, 2 = fp16 single
// =====================================================================================
template<int NMMA, int OMODE, bool BTRANS, bool ACONV, bool BIAS_M, bool BIAS_N,
         bool GELUF, bool ADDF, bool SCALEF>
__global__ void __launch_bounds__(128, 3)
tc2_gemm(const void* Ahv, const __half* Alo, long strideA, int lda,
         const __half* Bhi, const __half* Blo,
         int bDiv, long bHi, long bLo, int ldb,
         float* Cf, __half* Chi, __half* Clo,
         int cDiv, long cHi, long cLo, int ldc,
         const float* Add, const float* bias, int biasZ,
         float alpha, int M, int N, int K)
{
    constexpr int BN  = 64;
    constexpr int BK  = 32;
    constexpr int SKA = 40;
    constexpr int SN  = BN + 8;
    constexpr int ASZ = 128 * SKA;
    constexpr int BSZ = BTRANS ? (BK * SN) : (BN * SKA);
    constexpr int APL = (NMMA >= 2) ? 2 : 1;
    constexpr int BPL = (NMMA == 3) ? 2 : 1;
    constexpr int STAGE = APL * ASZ + BPL * BSZ;
    constexpr int MF = 4;
    constexpr int NF = 4;

    extern __shared__ __half sm[];

    const int tid = threadIdx.x, wid = tid >> 5, lid = tid & 31;
    const int wm = wid >> 1, wn = wid & 1;
    const int z = blockIdx.z;
    const int row0 = blockIdx.y * 128, col0 = blockIdx.x * BN;

    const __half* Ahi = ACONV ? nullptr : ((const __half*)Ahv + (long)z * strideA);
    const __half* Alz = (ACONV || APL == 1) ? nullptr : (Alo + (long)z * strideA);
    const float* Af = ACONV ? ((const float*)Ahv + (long)z * strideA) : nullptr;
    Bhi += (long)(z / bDiv) * bHi + (long)(z % bDiv) * bLo;
    if (NMMA == 3) Blo += (long)(z / bDiv) * bHi + (long)(z % bDiv) * bLo;
    const long coff = (long)(z / cDiv) * cHi + (long)(z % cDiv) * cLo;
    if (BIAS_N || BIAS_M) bias += (long)z * biasZ;

    const uint32_t smBase = smem_u32(sm);
    const int nIt = K / BK;

    float acc[MF][NF][4];
#pragma unroll
    for (int i = 0; i < MF; i++)
#pragma unroll
        for (int j = 0; j < NF; j++)
#pragma unroll
            for (int r = 0; r < 4; r++) acc[i][j][r] = 0.f;

    float4 av[8];

    auto issueTile = [&](int it, int st) {
        const int k0 = it * BK;
        const uint32_t sbase = smBase + (uint32_t)(st * STAGE) * 2;
        if (!ACONV) {
#pragma unroll
            for (int pl = 0; pl < APL; pl++) {
                const __half* Ag = pl ? Alz : Ahi;
                const uint32_t sd = sbase + (uint32_t)(pl * ASZ) * 2;
#pragma unroll
                for (int i = 0; i < 4; i++) {
                    int idx = tid + (i << 7);
                    int r = idx >> 2, c8 = (idx & 3) << 3;
                    cpa16(sd + (uint32_t)(r * SKA + c8) * 2,
                          Ag + (long)(row0 + r) * lda + k0 + c8);
                }
            }
        }
        if (BTRANS) {
#pragma unroll
            for (int pl = 0; pl < BPL; pl++) {
                const __half* Bg = pl ? Blo : Bhi;
                const uint32_t sd = sbase + (uint32_t)(APL * ASZ + pl * BSZ) * 2;
#pragma unroll
                for (int i = 0; i < 2; i++) {
                    int idx = tid + (i << 7);
                    int k = idx >> 3, c8 = (idx & 7) << 3;
                    cpa16(sd + (uint32_t)(k * SN + c8) * 2,
                          Bg + (long)(k0 + k) * ldb + col0 + c8);
                }
            }
        } else {
#pragma unroll
            for (int pl = 0; pl < BPL; pl++) {
                const __half* Bg = pl ? Blo : Bhi;
                const uint32_t sd = sbase + (uint32_t)(APL * ASZ + pl * BSZ) * 2;
#pragma unroll
                for (int i = 0; i < 2; i++) {
                    int idx = tid + (i << 7);
                    int r = idx >> 2, c8 = (idx & 3) << 3;
                    cpa16(sd + (uint32_t)(r * SKA + c8) * 2,
                          Bg + (long)(col0 + r) * ldb + k0 + c8);
                }
            }
        }
    };
    auto ldgA = [&](int it) {
        const int k0 = it * BK;
#pragma unroll
        for (int i = 0; i < 8; i++) {
            int idx = tid + (i << 7);
            int r = idx >> 3, c4 = (idx & 7) << 2;
            av[i] = *(const float4*)(Af + (long)(row0 + r) * lda + k0 + c4);
        }
    };
    auto stsA = [&](int st) {
        __half* sAhi = sm + st * STAGE;
        __half* sAlo = sAhi + ASZ;
#pragma unroll
        for (int i = 0; i < 8; i++) {
            int idx = tid + (i << 7);
            int r = idx >> 3, c4 = (idx & 7) << 2;
            if (APL == 2) {
                __half h[4], l[4];
                split1(av[i].x, h[0], l[0]); split1(av[i].y, h[1], l[1]);
                split1(av[i].z, h[2], l[2]); split1(av[i].w, h[3], l[3]);
                *(uint2*)(sAhi + r * SKA + c4) = *(uint2*)h;
                *(uint2*)(sAlo + r * SKA + c4) = *(uint2*)l;
            } else {
                __half h[4] = {__float2half_rn(av[i].x), __float2half_rn(av[i].y),
                               __float2half_rn(av[i].z), __float2half_rn(av[i].w)};
                *(uint2*)(sAhi + r * SKA + c4) = *(uint2*)h;
            }
        }
    };

    if (ACONV) { ldgA(0); stsA(0); }
    issueTile(0, 0);
    asm volatile("cp.async.commit_group;");

    for (int it = 0; it < nIt; it++) {
        const int s = it & 1;
        asm volatile("cp.async.wait_group 0;");
        __syncthreads();
        if (it + 1 < nIt) {
            if (ACONV) ldgA(it + 1);
            issueTile(it + 1, s ^ 1);
            asm volatile("cp.async.commit_group;");
        }

        const uint32_t base = smBase + (uint32_t)(s * STAGE) * 2;
        const uint32_t aHiB = base, aLoB = base + ASZ * 2;
        const uint32_t bHiB = base + APL * ASZ * 2, bLoB = bHiB + BSZ * 2;

#pragma unroll
        for (int ks = 0; ks < 2; ks++) {
            uint32_t ah[MF][4], al[MF][4], bh[NF][2], bl[NF][2];
#pragma unroll
            for (int mf = 0; mf < MF; mf++) {
                uint32_t off = (uint32_t)((wm * 64 + mf * 16 + (lid & 15)) * SKA
                                          + ks * 16 + (lid >> 4) * 8) * 2;
                ldsm4(aHiB + off, ah[mf][0], ah[mf][1], ah[mf][2], ah[mf][3]);
                if (APL == 2)
                    ldsm4(aLoB + off, al[mf][0], al[mf][1], al[mf][2], al[mf][3]);
            }
            if (BTRANS) {
#pragma unroll
                for (int p = 0; p < NF / 2; p++) {
                    uint32_t off = (uint32_t)((ks * 16 + (lid & 15)) * SN
                                              + wn * 32 + p * 16 + (lid >> 4) * 8) * 2;
                    ldsm4t(bHiB + off, bh[2*p][0], bh[2*p][1], bh[2*p+1][0], bh[2*p+1][1]);
                    if (NMMA == 3)
                        ldsm4t(bLoB + off, bl[2*p][0], bl[2*p][1], bl[2*p+1][0], bl[2*p+1][1]);
                }
            } else {
#pragma unroll
                for (int p = 0; p < NF / 2; p++) {
                    uint32_t off = (uint32_t)((wn * 32 + p * 16 + (lid & 7) + (lid >> 4) * 8) * SKA
                                              + ks * 16 + ((lid >> 3) & 1) * 8) * 2;
                    ldsm4(bHiB + off, bh[2*p][0], bh[2*p][1], bh[2*p+1][0], bh[2*p+1][1]);
                    if (NMMA == 3)
                        ldsm4(bLoB + off, bl[2*p][0], bl[2*p][1], bl[2*p+1][0], bl[2*p+1][1]);
                }
            }
#pragma unroll
            for (int mf = 0; mf < MF; mf++)
#pragma unroll
                for (int nf = 0; nf < NF; nf++)
                    mma16816(acc[mf][nf], ah[mf], bh[nf]);
            if (NMMA == 3) {
#pragma unroll
                for (int mf = 0; mf < MF; mf++)
#pragma unroll
                    for (int nf = 0; nf < NF; nf++)
                        mma16816(acc[mf][nf], ah[mf], bl[nf]);
            }
            if (NMMA >= 2) {
#pragma unroll
                for (int mf = 0; mf < MF; mf++)
#pragma unroll
                    for (int nf = 0; nf < NF; nf++)
                        mma16816(acc[mf][nf], al[mf], bh[nf]);
            }
        }
        if (ACONV && it + 1 < nIt) stsA(s ^ 1);
    }

    // ---- epilogue ----
    float* Cp = (OMODE == 0) ? (Cf + coff) : nullptr;
    __half* ChP = (OMODE != 0) ? (Chi + coff) : nullptr;
    __half* ClP = (OMODE == 1) ? (Clo + coff) : nullptr;
    const float* Ap2 = ADDF ? (Add + coff) : nullptr;
    const int rBase = row0 + wm * 64 + (lid >> 2);
    const int cBase = col0 + wn * 32 + (lid & 3) * 2;
#pragma unroll
    for (int mf = 0; mf < MF; mf++) {
#pragma unroll
        for (int half = 0; half < 2; half++) {
            const int gr = rBase + mf * 16 + half * 8;
            const float bm = BIAS_M ? bias[gr] : 0.f;
#pragma unroll
            for (int nf = 0; nf < NF; nf++) {
                const int gc = cBase + nf * 8;
                float v0 = acc[mf][nf][half * 2 + 0];
                float v1 = acc[mf][nf][half * 2 + 1];
                if (SCALEF) { v0 *= alpha; v1 *= alpha; }
                if (BIAS_M) { v0 += bm; v1 += bm; }
                if (BIAS_N) { v0 += bias[gc]; v1 += bias[gc + 1]; }
                if (GELUF) {
                    v0 = 0.5f * v0 * (1.0f + erff(v0 * 0.70710678118654752f));
                    v1 = 0.5f * v1 * (1.0f + erff(v1 * 0.70710678118654752f));
                }
                long off = (long)gr * ldc + gc;
                if (ADDF) { v0 += Ap2[off]; v1 += Ap2[off + 1]; }
                if (OMODE == 1) {
                    __half h0, l0, h1, l1;
                    split1(v0, h0, l0); split1(v1, h1, l1);
                    __half hp[2] = {h0, h1}, lp[2] = {l0, l1};
                    *(uint32_t*)(ChP + off) = *(uint32_t*)hp;
                    *(uint32_t*)(ClP + off) = *(uint32_t*)lp;
                } else if (OMODE == 2) {
                    __half hp[2] = {__float2half_rn(v0), __float2half_rn(v1)};
                    *(uint32_t*)(ChP + off) = *(uint32_t*)hp;
                } else {
                    *(float2*)(Cp + off) = make_float2(v0, v1);
                }
            }
        }
    }
}

// =====================================================================================
// Fused QK^T * 0.125 + softmax-one -> attn out. SINGLE-plane q/k, 1-MMA.
// grid (32, 64), 256 threads; Q fragments preloaded once. smem 43776 B.
// =====================================================================================
__global__ void __launch_bounds__(256, 1)
qk_softmax(const __half* __restrict__ qH, const __half* __restrict__ kH,
           float* __restrict__ attn)
{
    constexpr int SK = 72;
    constexpr int QPL = 32 * SK;          // 2304
    constexpr int KPL = 128 * SK;         // 9216
    extern __shared__ __half sm[];
    float* redA = (float*)(sm + QPL + 2 * KPL);
    float* redB = redA + 32 * 9;

    const int tid = threadIdx.x, wid = tid >> 5, lid = tid & 31;
    const int z = blockIdx.y;
    const int row0 = blockIdx.x * 32;
    const __half* Qh = qH + (long)z * 65536;
    const __half* Kh = kH + (long)z * 65536;
    attn += (long)z * 1048576;

    const uint32_t smBase = smem_u32(sm);

    {   // Q preload: 32x64 halves, one 16B chunk per thread
        int r = tid >> 3, c8 = (tid & 7) << 3;
        cpa16(smBase + (uint32_t)(r * SK + c8) * 2, Qh + (long)(row0 + r) * 64 + c8);
    }
    auto issueK = [&](int ch, int st) {
        const uint32_t sd = smBase + (uint32_t)(QPL + st * KPL) * 2;
#pragma unroll
        for (int i = 0; i < 4; i++) {
            int idx = tid + (i << 8);
            int r = idx >> 3, c8 = (idx & 7) << 3;
            cpa16(sd + (uint32_t)(r * SK + c8) * 2,
                  Kh + (long)(ch * 128 + r) * 64 + c8);
        }
    };
    issueK(0, 0);
    asm volatile("cp.async.commit_group;");

    float acc[2][8][2][4];
#pragma unroll
    for (int mf = 0; mf < 2; mf++)
#pragma unroll
        for (int ch = 0; ch < 8; ch++)
#pragma unroll
            for (int nf = 0; nf < 2; nf++)
#pragma unroll
                for (int r = 0; r < 4; r++) acc[mf][ch][nf][r] = 0.f;

    uint32_t aH[4][2][4];

    for (int ch = 0; ch < 8; ch++) {
        asm volatile("cp.async.wait_group 0;");
        __syncthreads();
        if (ch + 1 < 8) {
            issueK(ch + 1, (ch + 1) & 1);
            asm volatile("cp.async.commit_group;");
        }
        if (ch == 0) {
#pragma unroll
            for (int ks = 0; ks < 4; ks++)
#pragma unroll
                for (int mf = 0; mf < 2; mf++) {
                    uint32_t off = (uint32_t)((mf * 16 + (lid & 15)) * SK
                                              + ks * 16 + (lid >> 4) * 8) * 2;
                    ldsm4(smBase + off, aH[ks][mf][0], aH[ks][mf][1],
                                        aH[ks][mf][2], aH[ks][mf][3]);
                }
        }
        const uint32_t kB = smBase + (uint32_t)(QPL + (ch & 1) * KPL) * 2;
#pragma unroll
        for (int ks = 0; ks < 4; ks++) {
            uint32_t bh[2][2];
            uint32_t off = (uint32_t)((wid * 16 + (lid & 7) + (lid >> 4) * 8) * SK
                                      + ks * 16 + ((lid >> 3) & 1) * 8) * 2;
            ldsm4(kB + off, bh[0][0], bh[0][1], bh[1][0], bh[1][1]);
#pragma unroll
            for (int mf = 0; mf < 2; mf++)
#pragma unroll
                for (int nf = 0; nf < 2; nf++)
                    mma16816(acc[mf][ch][nf], aH[ks][mf], bh[nf]);
        }
    }

    // ---- softmax-one ----
    const int rq = lid >> 2, cq = lid & 3;
#pragma unroll
    for (int mf = 0; mf < 2; mf++)
#pragma unroll
        for (int ch = 0; ch < 8; ch++)
#pragma unroll
            for (int nf = 0; nf < 2; nf++)
#pragma unroll
                for (int r = 0; r < 4; r++) acc[mf][ch][nf][r] *= 0.125f;

    float mx[2][2];
#pragma unroll
    for (int mf = 0; mf < 2; mf++)
#pragma unroll
        for (int half = 0; half < 2; half++) {
            float m = -1e30f;
#pragma unroll
            for (int ch = 0; ch < 8; ch++)
#pragma unroll
                for (int nf = 0; nf < 2; nf++)
                    m = fmaxf(m, fmaxf(acc[mf][ch][nf][half*2], acc[mf][ch][nf][half*2+1]));
            m = fmaxf(m, __shfl_xor_sync(0xffffffffu, m, 1));
            m = fmaxf(m, __shfl_xor_sync(0xffffffffu, m, 2));
            mx[mf][half] = m;
        }
    if (cq == 0) {
#pragma unroll
        for (int mf = 0; mf < 2; mf++)
#pragma unroll
            for (int half = 0; half < 2; half++)
                redA[(mf * 16 + half * 8 + rq) * 9 + wid] = mx[mf][half];
    }
    __syncthreads();
#pragma unroll
    for (int mf = 0; mf < 2; mf++)
#pragma unroll
        for (int half = 0; half < 2; half++) {
            float m = -1e30f;
            const float* rr = redA + (mf * 16 + half * 8 + rq) * 9;
#pragma unroll
            for (int w = 0; w < 8; w++) m = fmaxf(m, rr[w]);
            mx[mf][half] = m;
        }

    float sum[2][2] = {{0.f, 0.f}, {0.f, 0.f}};
#pragma unroll
    for (int mf = 0; mf < 2; mf++)
#pragma unroll
        for (int half = 0; half < 2; half++) {
            const float m = mx[mf][half];
            float s = 0.f;
#pragma unroll
            for (int ch = 0; ch < 8; ch++)
#pragma unroll
                for (int nf = 0; nf < 2; nf++) {
                    float e0 = __expf(acc[mf][ch][nf][half*2]     - m);
                    float e1 = __expf(acc[mf][ch][nf][half*2 + 1] - m);
                    acc[mf][ch][nf][half*2]     = e0;
                    acc[mf][ch][nf][half*2 + 1] = e1;
                    s += e0 + e1;
                }
            s += __shfl_xor_sync(0xffffffffu, s, 1);
            s += __shfl_xor_sync(0xffffffffu, s, 2);
            sum[mf][half] = s;
        }
    if (cq == 0) {
#pragma unroll
        for (int mf = 0; mf < 2; mf++)
#pragma unroll
            for (int half = 0; half < 2; half++)
                redB[(mf * 16 + half * 8 + rq) * 9 + wid] = sum[mf][half];
    }
    __syncthreads();
#pragma unroll
    for (int mf = 0; mf < 2; mf++)
#pragma unroll
        for (int half = 0; half < 2; half++) {
            float s = 0.f;
            const float* rr = redB + (mf * 16 + half * 8 + rq) * 9;
#pragma unroll
            for (int w = 0; w < 8; w++) s += rr[w];
            sum[mf][half] = 1.0f / (1.0f + s);
        }

#pragma unroll
    for (int mf = 0; mf < 2; mf++)
#pragma unroll
        for (int half = 0; half < 2; half++) {
            const int gr = row0 + mf * 16 + half * 8 + rq;
            const float inv = sum[mf][half];
#pragma unroll
            for (int ch = 0; ch < 8; ch++)
#pragma unroll
                for (int nf = 0; nf < 2; nf++) {
                    const int gc = ch * 128 + wid * 16 + nf * 8 + cq * 2;
                    *(float2*)(attn + (long)gr * 1024 + gc) =
                        make_float2(acc[mf][ch][nf][half*2] * inv,
                                    acc[mf][ch][nf][half*2+1] * inv);
                }
        }
}

// =====================================================================================
__global__ void cvt_hi(const float* __restrict__ s, __half* __restrict__ hi, int n4)
{
    int i = blockIdx.x * 256 + threadIdx.x;
    if (i >= n4) return;
    float4 v = ((const float4*)s)[i];
    __half h[4] = {__float2half_rn(v.x), __float2half_rn(v.y),
                   __float2half_rn(v.z), __float2half_rn(v.w)};
    ((uint2*)hi)[i] = *(uint2*)h;
}

__global__ void bias_gather(const float* a, const float* b, const float* c, float* o)
{
    const float* src[3] = {a, b, c};
    o[blockIdx.x * 1024 + threadIdx.x] = src[blockIdx.x][threadIdx.x];
}

// =====================================================================================
__global__ void ln3_kernel(const float* __restrict__ x, int nOut,
    const float* __restrict__ w0, const float* __restrict__ b0,
    const float* __restrict__ w1, const float* __restrict__ b1,
    const float* __restrict__ w2, const float* __restrict__ b2,
    __half* __restrict__ oHi, __half* __restrict__ oLo)
{
    const int dx   = threadIdx.x & 31;
    const int lane = threadIdx.x >> 5;
    const int d    = blockIdx.x * 32 + dx;
    const long base = (long)blockIdx.y * CD + d;

    float s = 0.f, ss = 0.f;
    for (int c = lane; c < CC; c += 8) {
        float v = x[base + (long)c * DD];
        s += v; ss += v * v;
    }
    __shared__ float sS[8][33], sQ[8][33];
    sS[lane][dx] = s; sQ[lane][dx] = ss;
    __syncthreads();
    if (lane == 0) {
        float ts = 0.f, tq = 0.f;
        #pragma unroll
        for (int i = 0; i < 8; i++) { ts += sS[i][dx]; tq += sQ[i][dx]; }
        float mean = ts * (1.0f / CC);
        float var  = tq * (1.0f / CC) - mean * mean;
        sS[0][dx] = mean;
        sQ[0][dx] = rsqrtf(var + 1e-6f);
    }
    __syncthreads();
    const float mean = sS[0][dx];
    const float rstd = sQ[0][dx];
    const float* W[3] = {w0, w1, w2};
    const float* Bv[3] = {b0, b1, b2};
    for (int c = lane; c < CC; c += 8) {
        long idx = base + (long)c * DD;
        float xn = (x[idx] - mean) * rstd;
        for (int p = 0; p < nOut; p++) {
            float v = W[p][c] * xn + Bv[p][c];
            if (oLo) {
                __half h, l;
                split1(v, h, l);
                oHi[(long)p * BCD + idx] = h;
                oLo[(long)p * BCD + idx] = l;
            } else {
                oHi[(long)p * BCD + idx] = __float2half_rn(v);
            }
        }
    }
}

// =====================================================================================
extern "C" void kernel_launch(void* const* d_in, const int* in_sizes, int n_in,
                              void* d_out, int out_size)
{
    const float* x1      = (const float*)d_in[0];
    const float* lnq_w   = (const float*)d_in[1];
    const float* lnq_b   = (const float*)d_in[2];
    const float* lnk_w   = (const float*)d_in[3];
    const float* lnk_b   = (const float*)d_in[4];
    const float* lnv_w   = (const float*)d_in[5];
    const float* lnv_b   = (const float*)d_in[6];
    const float* wq      = (const float*)d_in[7];
    const float* bq      = (const float*)d_in[8];
    const float* wk      = (const float*)d_in[9];
    const float* bk      = (const float*)d_in[10];
    const float* wv      = (const float*)d_in[11];
    const float* bv      = (const float*)d_in[12];
    const float* ffnln_w = (const float*)d_in[13];
    const float* ffnln_b = (const float*)d_in[14];
    const float* conv1_w = (const float*)d_in[15];
    const float* conv1_b = (const float*)d_in[16];
    const float* conv2_w = (const float*)d_in[17];
    const float* conv2_b = (const float*)d_in[18];

    __half *lnHi, *lnLo, *qkvHi, *wHi;
    __half *c1wHi, *c2wHi, *xlHi, *h1Hi;
    float *xb, *bqkv;
    cudaGetSymbolAddress((void**)&lnHi,  g_ln_hi);   cudaGetSymbolAddress((void**)&lnLo,  g_ln_lo);
    cudaGetSymbolAddress((void**)&qkvHi, g_qkv_hi);
    cudaGetSymbolAddress((void**)&wHi,   g_w_hi);
    cudaGetSymbolAddress((void**)&c1wHi, g_c1w_hi);
    cudaGetSymbolAddress((void**)&c2wHi, g_c2w_hi);
    cudaGetSymbolAddress((void**)&xlHi,  g_xl_hi);
    cudaGetSymbolAddress((void**)&h1Hi,  g_h1_hi);
    cudaGetSymbolAddress((void**)&xb,    g_x);
    cudaGetSymbolAddress((void**)&bqkv,  g_bqkv);

    float* outx = (float*)d_out;
    float* attn = outx + (long)BCD;

    // Precision plan:
    //   QKV : NMMA=2 (A=ln hi/lo, B=w single) -> q/k/v SINGLE fp16 planes
    //   QK  : 1-MMA single planes (spends margin; attn logits already fp16-W limited)
    //   PV  : NMMA=1 (A=attn fp32 rounded in-kernel, B=v single)
    //   C1/C2: NMMA=1
    auto kQKV = tc2_gemm<2, 2, false, false, false, true,  false, false, false>;
    auto kPV  = tc2_gemm<1, 0, true,  true,  false, false, false, true,  false>;
    auto kC1  = tc2_gemm<1, 2, true,  false, true,  false, true,  false, false>;
    auto kC2  = tc2_gemm<1, 0, true,  false, true,  false, false, true,  false>;
    const int SM_KB  = 2 * (2 * 128 * 40 + 1 * 64 * 40) * 2;  // 51200 (QKV)
    const int SM_1TR = 2 * (1 * 128 * 40 + 1 * 32 * 72) * 2;  // 29696 (PV/C1/C2)
    const int SM_QS  = (32 * 72 + 2 * 128 * 72) * 2 + 2 * 32 * 9 * 4;  // 43776
    cudaFuncSetAttribute(kQKV, cudaFuncAttributeMaxDynamicSharedMemorySize, SM_KB);
    cudaFuncSetAttribute(kPV,  cudaFuncAttributeMaxDynamicSharedMemorySize, SM_1TR);
    cudaFuncSetAttribute(kC1,  cudaFuncAttributeMaxDynamicSharedMemorySize, SM_1TR);
    cudaFuncSetAttribute(kC2,  cudaFuncAttributeMaxDynamicSharedMemorySize, SM_1TR);
    cudaFuncSetAttribute(qk_softmax, cudaFuncAttributeMaxDynamicSharedMemorySize, SM_QS);

    // 0) weight converts + bias gather
    cvt_hi<<<CD / 4 / 256, 256>>>(wq, wHi,          CD / 4);
    cvt_hi<<<CD / 4 / 256, 256>>>(wk, wHi + CD,     CD / 4);
    cvt_hi<<<CD / 4 / 256, 256>>>(wv, wHi + 2 * CD, CD / 4);
    cvt_hi<<<4 * CD / 4 / 256, 256>>>(conv1_w, c1wHi, 4 * CD / 4);
    cvt_hi<<<4 * CD / 4 / 256, 256>>>(conv2_w, c2wHi, 4 * CD / 4);
    bias_gather<<<3, 1024>>>(bq, bk, bv, bqkv);

    // 1) QKV LayerNorms -> hi/lo planes
    dim3 lng(DD / 32, BB);
    ln3_kernel<<<lng, 256>>>(x1, 3, lnq_w, lnq_b, lnk_w, lnk_b, lnv_w, lnv_b, lnHi, lnLo);

    // 2) fused QKV linears (z = 0/1/2), 2-MMA, single-plane output
    dim3 gqkv(16, 32, 3);
    kQKV<<<gqkv, 128, SM_KB>>>(lnHi, lnLo, BCD, 1024, wHi, nullptr, 1, CD, 0, 1024,
                               nullptr, qkvHi, nullptr, 1, BCD, 0, 1024,
                               nullptr, bqkv, 1024, 1.f, 4096, 1024, 1024);

    // 3+4) fused S = softmax_one(0.125 * Q K^T), 1-MMA -> attn output
    dim3 gqs(32, BB * HH);
    qk_softmax<<<gqs, 256, SM_QS>>>(qkvHi, qkvHi + BCD, attn);

    // 5) O = P V (1-MMA), scatter to x[b, i, h*64+e], fused residual add of x1
    dim3 gpv(1, 8, BB * HH);
    kPV<<<gpv, 128, SM_1TR>>>(attn, nullptr, 1048576, 1024,
                              qkvHi + 2 * (long)BCD, nullptr, 1, 65536, 0, 64,
                              xb, nullptr, nullptr, 16, CD, 64, 1024,
                              x1, nullptr, 0, 1.f, 1024, 64, 1024);

    // 6) FFN LayerNorm -> xl single plane
    ln3_kernel<<<lng, 256>>>(xb, 1, ffnln_w, ffnln_b, nullptr, nullptr, nullptr, nullptr,
                             xlHi, nullptr);

    // 7) conv1: h1 = GELU(W1 @ xl_z + b1) (1-MMA, single fp16 out)
    dim3 gc1(16, 32, BB);
    kC1<<<gc1, 128, SM_1TR>>>(c1wHi, nullptr, 0, 1024, xlHi, nullptr, 1, CD, 0, 1024,
                              nullptr, h1Hi, nullptr, 1, (long)4096 * 1024, 0, 1024,
                              nullptr, conv1_b, 0, 1.f, 4096, 1024, 1024);

    // 8) conv2 + residual: out = x + (W2 @ h1_z + b2) (1-MMA)
    dim3 gc2(16, 8, BB);
    kC2<<<gc2, 128, SM_1TR>>>(c2wHi, nullptr, 0, 4096, h1Hi, nullptr, 1, (long)4096 * 1024, 0, 1024,
                              outx, nullptr, nullptr, 1, CD, 0, 1024,
                              xb, conv2_b, 0, 1.f, 1024, 1024, 4096);
}

// round 14
// speedup vs baseline: 1.1272x; 1.0758x over previous
#include <cuda_runtime.h>
#include <cuda_fp16.h>
#include <math.h>
#include <stdint.h>

#define BB   4
#define CC   1024
#define DD   1024
#define HH   16
#define CD   (CC*DD)          // 1048576
#define BCD  (BB*CD)          // 4194304
#define H1SZ (BB*4096*1024)   // 16777216

// ---------------- scratch (static __device__ arrays; no runtime alloc) ---------------
__device__ __half g_ln_hi[3*BCD];                  // lnq/lnk/lnv single fp16 planes
__device__ __half g_qkv_hi[3*BCD];                 // q/k/v single fp16 planes
__device__ __half g_w_hi[3*CD];
__device__ __half g_c1w_hi[4*CD];
__device__ __half g_c2w_hi[4*CD];
__device__ __half g_xl_hi[BCD];
__device__ __half g_h1_hi[H1SZ];
__device__ float g_x[BCD];
__device__ float g_bqkv[3*1024];

// =====================================================================================
// helpers
// =====================================================================================
__device__ __forceinline__ uint32_t smem_u32(const void* p) {
    uint32_t a;
    asm("{ .reg .u64 t; cvta.to.shared.u64 t, %1; cvt.u32.u64 %0, t; }" : "=r"(a) : "l"(p));
    return a;
}
__device__ __forceinline__ void cpa16(uint32_t s, const void* g) {
    asm volatile("cp.async.cg.shared.global [%0], [%1], 16;" :: "r"(s), "l"(g));
}
__device__ __forceinline__ void ldsm4(uint32_t addr, uint32_t& r0, uint32_t& r1,
                                      uint32_t& r2, uint32_t& r3) {
    asm volatile("ldmatrix.sync.aligned.m8n8.x4.shared.b16 {%0,%1,%2,%3}, [%4];"
                 : "=r"(r0), "=r"(r1), "=r"(r2), "=r"(r3) : "r"(addr));
}
__device__ __forceinline__ void ldsm4t(uint32_t addr, uint32_t& r0, uint32_t& r1,
                                       uint32_t& r2, uint32_t& r3) {
    asm volatile("ldmatrix.sync.aligned.m8n8.x4.trans.shared.b16 {%0,%1,%2,%3}, [%4];"
                 : "=r"(r0), "=r"(r1), "=r"(r2), "=r"(r3) : "r"(addr));
}
__device__ __forceinline__ void mma16816(float* c, const uint32_t* a, const uint32_t* b) {
    asm volatile(
        "mma.sync.aligned.m16n8k16.row.col.f32.f16.f16.f32 "
        "{%0,%1,%2,%3}, {%4,%5,%6,%7}, {%8,%9}, {%0,%1,%2,%3};"
        : "+f"(c[0]), "+f"(c[1]), "+f"(c[2]), "+f"(c[3])
        : "r"(a[0]), "r"(a[1]), "r"(a[2]), "r"(a[3]), "r"(b[0]), "r"(b[1]));
}
__device__ __forceinline__ void split1(float v, __half& h, __half& l) {
    h = __float2half_rn(v);
    l = __float2half_rn(v - __half2float(h));
}

// =====================================================================================
// Tensor-core GEMM (R11 shell): block 128x64, 4 warps, BK=32, 2-stage cp.async
// race-free, 3 CTAs/SM.
//   NMMA=1: D = a*b ; NMMA=2: D = (a_hi+a_lo)*b ; NMMA=3: + a_hi*b_lo
//   OMODE: 0 = fp32, 1 = fp16 hi/lo, 2 = fp16 single
// =====================================================================================
template<int NMMA, int OMODE, bool BTRANS, bool ACONV, bool BIAS_M, bool BIAS_N,
         bool GELUF, bool ADDF, bool SCALEF>
__global__ void __launch_bounds__(128, 3)
tc2_gemm(const void* Ahv, const __half* Alo, long strideA, int lda,
         const __half* Bhi, const __half* Blo,
         int bDiv, long bHi, long bLo, int ldb,
         float* Cf, __half* Chi, __half* Clo,
         int cDiv, long cHi, long cLo, int ldc,
         const float* Add, const float* bias, int biasZ,
         float alpha, int M, int N, int K)
{
    constexpr int BN  = 64;
    constexpr int BK  = 32;
    constexpr int SKA = 40;
    constexpr int SN  = BN + 8;
    constexpr int ASZ = 128 * SKA;
    constexpr int BSZ = BTRANS ? (BK * SN) : (BN * SKA);
    constexpr int APL = (NMMA >= 2) ? 2 : 1;
    constexpr int BPL = (NMMA == 3) ? 2 : 1;
    constexpr int STAGE = APL * ASZ + BPL * BSZ;
    constexpr int MF = 4;
    constexpr int NF = 4;

    extern __shared__ __half sm[];

    const int tid = threadIdx.x, wid = tid >> 5, lid = tid & 31;
    const int wm = wid >> 1, wn = wid & 1;
    const int z = blockIdx.z;
    const int row0 = blockIdx.y * 128, col0 = blockIdx.x * BN;

    const __half* Ahi = ACONV ? nullptr : ((const __half*)Ahv + (long)z * strideA);
    const __half* Alz = (ACONV || APL == 1) ? nullptr : (Alo + (long)z * strideA);
    const float* Af = ACONV ? ((const float*)Ahv + (long)z * strideA) : nullptr;
    Bhi += (long)(z / bDiv) * bHi + (long)(z % bDiv) * bLo;
    if (NMMA == 3) Blo += (long)(z / bDiv) * bHi + (long)(z % bDiv) * bLo;
    const long coff = (long)(z / cDiv) * cHi + (long)(z % cDiv) * cLo;
    if (BIAS_N || BIAS_M) bias += (long)z * biasZ;

    const uint32_t smBase = smem_u32(sm);
    const int nIt = K / BK;

    float acc[MF][NF][4];
#pragma unroll
    for (int i = 0; i < MF; i++)
#pragma unroll
        for (int j = 0; j < NF; j++)
#pragma unroll
            for (int r = 0; r < 4; r++) acc[i][j][r] = 0.f;

    float4 av[8];

    auto issueTile = [&](int it, int st) {
        const int k0 = it * BK;
        const uint32_t sbase = smBase + (uint32_t)(st * STAGE) * 2;
        if (!ACONV) {
#pragma unroll
            for (int pl = 0; pl < APL; pl++) {
                const __half* Ag = pl ? Alz : Ahi;
                const uint32_t sd = sbase + (uint32_t)(pl * ASZ) * 2;
#pragma unroll
                for (int i = 0; i < 4; i++) {
                    int idx = tid + (i << 7);
                    int r = idx >> 2, c8 = (idx & 3) << 3;
                    cpa16(sd + (uint32_t)(r * SKA + c8) * 2,
                          Ag + (long)(row0 + r) * lda + k0 + c8);
                }
            }
        }
        if (BTRANS) {
#pragma unroll
            for (int pl = 0; pl < BPL; pl++) {
                const __half* Bg = pl ? Blo : Bhi;
                const uint32_t sd = sbase + (uint32_t)(APL * ASZ + pl * BSZ) * 2;
#pragma unroll
                for (int i = 0; i < 2; i++) {
                    int idx = tid + (i << 7);
                    int k = idx >> 3, c8 = (idx & 7) << 3;
                    cpa16(sd + (uint32_t)(k * SN + c8) * 2,
                          Bg + (long)(k0 + k) * ldb + col0 + c8);
                }
            }
        } else {
#pragma unroll
            for (int pl = 0; pl < BPL; pl++) {
                const __half* Bg = pl ? Blo : Bhi;
                const uint32_t sd = sbase + (uint32_t)(APL * ASZ + pl * BSZ) * 2;
#pragma unroll
                for (int i = 0; i < 2; i++) {
                    int idx = tid + (i << 7);
                    int r = idx >> 2, c8 = (idx & 3) << 3;
                    cpa16(sd + (uint32_t)(r * SKA + c8) * 2,
                          Bg + (long)(col0 + r) * ldb + k0 + c8);
                }
            }
        }
    };
    auto ldgA = [&](int it) {
        const int k0 = it * BK;
#pragma unroll
        for (int i = 0; i < 8; i++) {
            int idx = tid + (i << 7);
            int r = idx >> 3, c4 = (idx & 7) << 2;
            av[i] = *(const float4*)(Af + (long)(row0 + r) * lda + k0 + c4);
        }
    };
    auto stsA = [&](int st) {
        __half* sAhi = sm + st * STAGE;
        __half* sAlo = sAhi + ASZ;
#pragma unroll
        for (int i = 0; i < 8; i++) {
            int idx = tid + (i << 7);
            int r = idx >> 3, c4 = (idx & 7) << 2;
            if (APL == 2) {
                __half h[4], l[4];
                split1(av[i].x, h[0], l[0]); split1(av[i].y, h[1], l[1]);
                split1(av[i].z, h[2], l[2]); split1(av[i].w, h[3], l[3]);
                *(uint2*)(sAhi + r * SKA + c4) = *(uint2*)h;
                *(uint2*)(sAlo + r * SKA + c4) = *(uint2*)l;
            } else {
                __half h[4] = {__float2half_rn(av[i].x), __float2half_rn(av[i].y),
                               __float2half_rn(av[i].z), __float2half_rn(av[i].w)};
                *(uint2*)(sAhi + r * SKA + c4) = *(uint2*)h;
            }
        }
    };

    if (ACONV) { ldgA(0); stsA(0); }
    issueTile(0, 0);
    asm volatile("cp.async.commit_group;");

    for (int it = 0; it < nIt; it++) {
        const int s = it & 1;
        asm volatile("cp.async.wait_group 0;");
        __syncthreads();
        if (it + 1 < nIt) {
            if (ACONV) ldgA(it + 1);
            issueTile(it + 1, s ^ 1);
            asm volatile("cp.async.commit_group;");
        }

        const uint32_t base = smBase + (uint32_t)(s * STAGE) * 2;
        const uint32_t aHiB = base, aLoB = base + ASZ * 2;
        const uint32_t bHiB = base + APL * ASZ * 2, bLoB = bHiB + BSZ * 2;

#pragma unroll
        for (int ks = 0; ks < 2; ks++) {
            uint32_t ah[MF][4], al[MF][4], bh[NF][2], bl[NF][2];
#pragma unroll
            for (int mf = 0; mf < MF; mf++) {
                uint32_t off = (uint32_t)((wm * 64 + mf * 16 + (lid & 15)) * SKA
                                          + ks * 16 + (lid >> 4) * 8) * 2;
                ldsm4(aHiB + off, ah[mf][0], ah[mf][1], ah[mf][2], ah[mf][3]);
                if (APL == 2)
                    ldsm4(aLoB + off, al[mf][0], al[mf][1], al[mf][2], al[mf][3]);
            }
            if (BTRANS) {
#pragma unroll
                for (int p = 0; p < NF / 2; p++) {
                    uint32_t off = (uint32_t)((ks * 16 + (lid & 15)) * SN
                                              + wn * 32 + p * 16 + (lid >> 4) * 8) * 2;
                    ldsm4t(bHiB + off, bh[2*p][0], bh[2*p][1], bh[2*p+1][0], bh[2*p+1][1]);
                    if (NMMA == 3)
                        ldsm4t(bLoB + off, bl[2*p][0], bl[2*p][1], bl[2*p+1][0], bl[2*p+1][1]);
                }
            } else {
#pragma unroll
                for (int p = 0; p < NF / 2; p++) {
                    uint32_t off = (uint32_t)((wn * 32 + p * 16 + (lid & 7) + (lid >> 4) * 8) * SKA
                                              + ks * 16 + ((lid >> 3) & 1) * 8) * 2;
                    ldsm4(bHiB + off, bh[2*p][0], bh[2*p][1], bh[2*p+1][0], bh[2*p+1][1]);
                    if (NMMA == 3)
                        ldsm4(bLoB + off, bl[2*p][0], bl[2*p][1], bl[2*p+1][0], bl[2*p+1][1]);
                }
            }
#pragma unroll
            for (int mf = 0; mf < MF; mf++)
#pragma unroll
                for (int nf = 0; nf < NF; nf++)
                    mma16816(acc[mf][nf], ah[mf], bh[nf]);
            if (NMMA == 3) {
#pragma unroll
                for (int mf = 0; mf < MF; mf++)
#pragma unroll
                    for (int nf = 0; nf < NF; nf++)
                        mma16816(acc[mf][nf], ah[mf], bl[nf]);
            }
            if (NMMA >= 2) {
#pragma unroll
                for (int mf = 0; mf < MF; mf++)
#pragma unroll
                    for (int nf = 0; nf < NF; nf++)
                        mma16816(acc[mf][nf], al[mf], bh[nf]);
            }
        }
        if (ACONV && it + 1 < nIt) stsA(s ^ 1);
    }

    // ---- epilogue ----
    float* Cp = (OMODE == 0) ? (Cf + coff) : nullptr;
    __half* ChP = (OMODE != 0) ? (Chi + coff) : nullptr;
    __half* ClP = (OMODE == 1) ? (Clo + coff) : nullptr;
    const float* Ap2 = ADDF ? (Add + coff) : nullptr;
    const int rBase = row0 + wm * 64 + (lid >> 2);
    const int cBase = col0 + wn * 32 + (lid & 3) * 2;
#pragma unroll
    for (int mf = 0; mf < MF; mf++) {
#pragma unroll
        for (int half = 0; half < 2; half++) {
            const int gr = rBase + mf * 16 + half * 8;
            const float bm = BIAS_M ? bias[gr] : 0.f;
#pragma unroll
            for (int nf = 0; nf < NF; nf++) {
                const int gc = cBase + nf * 8;
                float v0 = acc[mf][nf][half * 2 + 0];
                float v1 = acc[mf][nf][half * 2 + 1];
                if (SCALEF) { v0 *= alpha; v1 *= alpha; }
                if (BIAS_M) { v0 += bm; v1 += bm; }
                if (BIAS_N) { v0 += bias[gc]; v1 += bias[gc + 1]; }
                if (GELUF) {
                    v0 = 0.5f * v0 * (1.0f + erff(v0 * 0.70710678118654752f));
                    v1 = 0.5f * v1 * (1.0f + erff(v1 * 0.70710678118654752f));
                }
                long off = (long)gr * ldc + gc;
                if (ADDF) { v0 += Ap2[off]; v1 += Ap2[off + 1]; }
                if (OMODE == 1) {
                    __half h0, l0, h1, l1;
                    split1(v0, h0, l0); split1(v1, h1, l1);
                    __half hp[2] = {h0, h1}, lp[2] = {l0, l1};
                    *(uint32_t*)(ChP + off) = *(uint32_t*)hp;
                    *(uint32_t*)(ClP + off) = *(uint32_t*)lp;
                } else if (OMODE == 2) {
                    __half hp[2] = {__float2half_rn(v0), __float2half_rn(v1)};
                    *(uint32_t*)(ChP + off) = *(uint32_t*)hp;
                } else {
                    *(float2*)(Cp + off) = make_float2(v0, v1);
                }
            }
        }
    }
}

// =====================================================================================
// Fused QK^T * 0.125 + softmax-one -> attn out. Single-plane q/k, 1-MMA (R13).
// =====================================================================================
__global__ void __launch_bounds__(256, 1)
qk_softmax(const __half* __restrict__ qH, const __half* __restrict__ kH,
           float* __restrict__ attn)
{
    constexpr int SK = 72;
    constexpr int QPL = 32 * SK;
    constexpr int KPL = 128 * SK;
    extern __shared__ __half sm[];
    float* redA = (float*)(sm + QPL + 2 * KPL);
    float* redB = redA + 32 * 9;

    const int tid = threadIdx.x, wid = tid >> 5, lid = tid & 31;
    const int z = blockIdx.y;
    const int row0 = blockIdx.x * 32;
    const __half* Qh = qH + (long)z * 65536;
    const __half* Kh = kH + (long)z * 65536;
    attn += (long)z * 1048576;

    const uint32_t smBase = smem_u32(sm);

    {
        int r = tid >> 3, c8 = (tid & 7) << 3;
        cpa16(smBase + (uint32_t)(r * SK + c8) * 2, Qh + (long)(row0 + r) * 64 + c8);
    }
    auto issueK = [&](int ch, int st) {
        const uint32_t sd = smBase + (uint32_t)(QPL + st * KPL) * 2;
#pragma unroll
        for (int i = 0; i < 4; i++) {
            int idx = tid + (i << 8);
            int r = idx >> 3, c8 = (idx & 7) << 3;
            cpa16(sd + (uint32_t)(r * SK + c8) * 2,
                  Kh + (long)(ch * 128 + r) * 64 + c8);
        }
    };
    issueK(0, 0);
    asm volatile("cp.async.commit_group;");

    float acc[2][8][2][4];
#pragma unroll
    for (int mf = 0; mf < 2; mf++)
#pragma unroll
        for (int ch = 0; ch < 8; ch++)
#pragma unroll
            for (int nf = 0; nf < 2; nf++)
#pragma unroll
                for (int r = 0; r < 4; r++) acc[mf][ch][nf][r] = 0.f;

    uint32_t aH[4][2][4];

    for (int ch = 0; ch < 8; ch++) {
        asm volatile("cp.async.wait_group 0;");
        __syncthreads();
        if (ch + 1 < 8) {
            issueK(ch + 1, (ch + 1) & 1);
            asm volatile("cp.async.commit_group;");
        }
        if (ch == 0) {
#pragma unroll
            for (int ks = 0; ks < 4; ks++)
#pragma unroll
                for (int mf = 0; mf < 2; mf++) {
                    uint32_t off = (uint32_t)((mf * 16 + (lid & 15)) * SK
                                              + ks * 16 + (lid >> 4) * 8) * 2;
                    ldsm4(smBase + off, aH[ks][mf][0], aH[ks][mf][1],
                                        aH[ks][mf][2], aH[ks][mf][3]);
                }
        }
        const uint32_t kB = smBase + (uint32_t)(QPL + (ch & 1) * KPL) * 2;
#pragma unroll
        for (int ks = 0; ks < 4; ks++) {
            uint32_t bh[2][2];
            uint32_t off = (uint32_t)((wid * 16 + (lid & 7) + (lid >> 4) * 8) * SK
                                      + ks * 16 + ((lid >> 3) & 1) * 8) * 2;
            ldsm4(kB + off, bh[0][0], bh[0][1], bh[1][0], bh[1][1]);
#pragma unroll
            for (int mf = 0; mf < 2; mf++)
#pragma unroll
                for (int nf = 0; nf < 2; nf++)
                    mma16816(acc[mf][ch][nf], aH[ks][mf], bh[nf]);
        }
    }

    // ---- softmax-one ----
    const int rq = lid >> 2, cq = lid & 3;
#pragma unroll
    for (int mf = 0; mf < 2; mf++)
#pragma unroll
        for (int ch = 0; ch < 8; ch++)
#pragma unroll
            for (int nf = 0; nf < 2; nf++)
#pragma unroll
                for (int r = 0; r < 4; r++) acc[mf][ch][nf][r] *= 0.125f;

    float mx[2][2];
#pragma unroll
    for (int mf = 0; mf < 2; mf++)
#pragma unroll
        for (int half = 0; half < 2; half++) {
            float m = -1e30f;
#pragma unroll
            for (int ch = 0; ch < 8; ch++)
#pragma unroll
                for (int nf = 0; nf < 2; nf++)
                    m = fmaxf(m, fmaxf(acc[mf][ch][nf][half*2], acc[mf][ch][nf][half*2+1]));
            m = fmaxf(m, __shfl_xor_sync(0xffffffffu, m, 1));
            m = fmaxf(m, __shfl_xor_sync(0xffffffffu, m, 2));
            mx[mf][half] = m;
        }
    if (cq == 0) {
#pragma unroll
        for (int mf = 0; mf < 2; mf++)
#pragma unroll
            for (int half = 0; half < 2; half++)
                redA[(mf * 16 + half * 8 + rq) * 9 + wid] = mx[mf][half];
    }
    __syncthreads();
#pragma unroll
    for (int mf = 0; mf < 2; mf++)
#pragma unroll
        for (int half = 0; half < 2; half++) {
            float m = -1e30f;
            const float* rr = redA + (mf * 16 + half * 8 + rq) * 9;
#pragma unroll
            for (int w = 0; w < 8; w++) m = fmaxf(m, rr[w]);
            mx[mf][half] = m;
        }

    float sum[2][2] = {{0.f, 0.f}, {0.f, 0.f}};
#pragma unroll
    for (int mf = 0; mf < 2; mf++)
#pragma unroll
        for (int half = 0; half < 2; half++) {
            const float m = mx[mf][half];
            float s = 0.f;
#pragma unroll
            for (int ch = 0; ch < 8; ch++)
#pragma unroll
                for (int nf = 0; nf < 2; nf++) {
                    float e0 = __expf(acc[mf][ch][nf][half*2]     - m);
                    float e1 = __expf(acc[mf][ch][nf][half*2 + 1] - m);
                    acc[mf][ch][nf][half*2]     = e0;
                    acc[mf][ch][nf][half*2 + 1] = e1;
                    s += e0 + e1;
                }
            s += __shfl_xor_sync(0xffffffffu, s, 1);
            s += __shfl_xor_sync(0xffffffffu, s, 2);
            sum[mf][half] = s;
        }
    if (cq == 0) {
#pragma unroll
        for (int mf = 0; mf < 2; mf++)
#pragma unroll
            for (int half = 0; half < 2; half++)
                redB[(mf * 16 + half * 8 + rq) * 9 + wid] = sum[mf][half];
    }
    __syncthreads();
#pragma unroll
    for (int mf = 0; mf < 2; mf++)
#pragma unroll
        for (int half = 0; half < 2; half++) {
            float s = 0.f;
            const float* rr = redB + (mf * 16 + half * 8 + rq) * 9;
#pragma unroll
            for (int w = 0; w < 8; w++) s += rr[w];
            sum[mf][half] = 1.0f / (1.0f + s);
        }

#pragma unroll
    for (int mf = 0; mf < 2; mf++)
#pragma unroll
        for (int half = 0; half < 2; half++) {
            const int gr = row0 + mf * 16 + half * 8 + rq;
            const float inv = sum[mf][half];
#pragma unroll
            for (int ch = 0; ch < 8; ch++)
#pragma unroll
                for (int nf = 0; nf < 2; nf++) {
                    const int gc = ch * 128 + wid * 16 + nf * 8 + cq * 2;
                    *(float2*)(attn + (long)gr * 1024 + gc) =
                        make_float2(acc[mf][ch][nf][half*2] * inv,
                                    acc[mf][ch][nf][half*2+1] * inv);
                }
        }
}

// =====================================================================================
__global__ void cvt_hi(const float* __restrict__ s, __half* __restrict__ hi, int n4)
{
    int i = blockIdx.x * 256 + threadIdx.x;
    if (i >= n4) return;
    float4 v = ((const float4*)s)[i];
    __half h[4] = {__float2half_rn(v.x), __float2half_rn(v.y),
                   __float2half_rn(v.z), __float2half_rn(v.w)};
    ((uint2*)hi)[i] = *(uint2*)h;
}

__global__ void bias_gather(const float* a, const float* b, const float* c, float* o)
{
    const float* src[3] = {a, b, c};
    o[blockIdx.x * 1024 + threadIdx.x] = src[blockIdx.x][threadIdx.x];
}

// =====================================================================================
// channel LayerNorm -> fp16 single planes (up to 3)
// =====================================================================================
__global__ void ln3_kernel(const float* __restrict__ x, int nOut,
    const float* __restrict__ w0, const float* __restrict__ b0,
    const float* __restrict__ w1, const float* __restrict__ b1,
    const float* __restrict__ w2, const float* __restrict__ b2,
    __half* __restrict__ oHi)
{
    const int dx   = threadIdx.x & 31;
    const int lane = threadIdx.x >> 5;
    const int d    = blockIdx.x * 32 + dx;
    const long base = (long)blockIdx.y * CD + d;

    float s = 0.f, ss = 0.f;
    for (int c = lane; c < CC; c += 8) {
        float v = x[base + (long)c * DD];
        s += v; ss += v * v;
    }
    __shared__ float sS[8][33], sQ[8][33];
    sS[lane][dx] = s; sQ[lane][dx] = ss;
    __syncthreads();
    if (lane == 0) {
        float ts = 0.f, tq = 0.f;
        #pragma unroll
        for (int i = 0; i < 8; i++) { ts += sS[i][dx]; tq += sQ[i][dx]; }
        float mean = ts * (1.0f / CC);
        float var  = tq * (1.0f / CC) - mean * mean;
        sS[0][dx] = mean;
        sQ[0][dx] = rsqrtf(var + 1e-6f);
    }
    __syncthreads();
    const float mean = sS[0][dx];
    const float rstd = sQ[0][dx];
    const float* W[3] = {w0, w1, w2};
    const float* Bv[3] = {b0, b1, b2};
    for (int c = lane; c < CC; c += 8) {
        long idx = base + (long)c * DD;
        float xn = (x[idx] - mean) * rstd;
        for (int p = 0; p < nOut; p++)
            oHi[(long)p * BCD + idx] = __float2half_rn(W[p][c] * xn + Bv[p][c]);
    }
}

// =====================================================================================
extern "C" void kernel_launch(void* const* d_in, const int* in_sizes, int n_in,
                              void* d_out, int out_size)
{
    const float* x1      = (const float*)d_in[0];
    const float* lnq_w   = (const float*)d_in[1];
    const float* lnq_b   = (const float*)d_in[2];
    const float* lnk_w   = (const float*)d_in[3];
    const float* lnk_b   = (const float*)d_in[4];
    const float* lnv_w   = (const float*)d_in[5];
    const float* lnv_b   = (const float*)d_in[6];
    const float* wq      = (const float*)d_in[7];
    const float* bq      = (const float*)d_in[8];
    const float* wk      = (const float*)d_in[9];
    const float* bk      = (const float*)d_in[10];
    const float* wv      = (const float*)d_in[11];
    const float* bv      = (const float*)d_in[12];
    const float* ffnln_w = (const float*)d_in[13];
    const float* ffnln_b = (const float*)d_in[14];
    const float* conv1_w = (const float*)d_in[15];
    const float* conv1_b = (const float*)d_in[16];
    const float* conv2_w = (const float*)d_in[17];
    const float* conv2_b = (const float*)d_in[18];

    __half *lnHi, *qkvHi, *wHi;
    __half *c1wHi, *c2wHi, *xlHi, *h1Hi;
    float *xb, *bqkv;
    cudaGetSymbolAddress((void**)&lnHi,  g_ln_hi);
    cudaGetSymbolAddress((void**)&qkvHi, g_qkv_hi);
    cudaGetSymbolAddress((void**)&wHi,   g_w_hi);
    cudaGetSymbolAddress((void**)&c1wHi, g_c1w_hi);
    cudaGetSymbolAddress((void**)&c2wHi, g_c2w_hi);
    cudaGetSymbolAddress((void**)&xlHi,  g_xl_hi);
    cudaGetSymbolAddress((void**)&h1Hi,  g_h1_hi);
    cudaGetSymbolAddress((void**)&xb,    g_x);
    cudaGetSymbolAddress((void**)&bqkv,  g_bqkv);

    float* outx = (float*)d_out;
    float* attn = outx + (long)BCD;

    // Precision plan (all single fp16 operands now):
    //   QKV : NMMA=1 ; QK : 1-MMA ; PV : NMMA=1 ; C1/C2 : NMMA=1
    auto kQKV = tc2_gemm<1, 2, false, false, false, true,  false, false, false>;
    auto kPV  = tc2_gemm<1, 0, true,  true,  false, false, false, true,  false>;
    auto kC1  = tc2_gemm<1, 2, true,  false, true,  false, true,  false, false>;
    auto kC2  = tc2_gemm<1, 0, true,  false, true,  false, false, true,  false>;
    const int SM_1KB = 2 * (1 * 128 * 40 + 1 * 64 * 40) * 2;  // 30720 (QKV)
    const int SM_1TR = 2 * (1 * 128 * 40 + 1 * 32 * 72) * 2;  // 29696 (PV/C1/C2)
    const int SM_QS  = (32 * 72 + 2 * 128 * 72) * 2 + 2 * 32 * 9 * 4;  // 43776
    cudaFuncSetAttribute(kQKV, cudaFuncAttributeMaxDynamicSharedMemorySize, SM_1KB);
    cudaFuncSetAttribute(kPV,  cudaFuncAttributeMaxDynamicSharedMemorySize, SM_1TR);
    cudaFuncSetAttribute(kC1,  cudaFuncAttributeMaxDynamicSharedMemorySize, SM_1TR);
    cudaFuncSetAttribute(kC2,  cudaFuncAttributeMaxDynamicSharedMemorySize, SM_1TR);
    cudaFuncSetAttribute(qk_softmax, cudaFuncAttributeMaxDynamicSharedMemorySize, SM_QS);

    // 0) weight converts + bias gather
    cvt_hi<<<CD / 4 / 256, 256>>>(wq, wHi,          CD / 4);
    cvt_hi<<<CD / 4 / 256, 256>>>(wk, wHi + CD,     CD / 4);
    cvt_hi<<<CD / 4 / 256, 256>>>(wv, wHi + 2 * CD, CD / 4);
    cvt_hi<<<4 * CD / 4 / 256, 256>>>(conv1_w, c1wHi, 4 * CD / 4);
    cvt_hi<<<4 * CD / 4 / 256, 256>>>(conv2_w, c2wHi, 4 * CD / 4);
    bias_gather<<<3, 1024>>>(bq, bk, bv, bqkv);

    // 1) QKV LayerNorms -> single fp16 planes
    dim3 lng(DD / 32, BB);
    ln3_kernel<<<lng, 256>>>(x1, 3, lnq_w, lnq_b, lnk_w, lnk_b, lnv_w, lnv_b, lnHi);

    // 2) fused QKV linears (z = 0/1/2), 1-MMA, single-plane output
    dim3 gqkv(16, 32, 3);
    kQKV<<<gqkv, 128, SM_1KB>>>(lnHi, nullptr, BCD, 1024, wHi, nullptr, 1, CD, 0, 1024,
                                nullptr, qkvHi, nullptr, 1, BCD, 0, 1024,
                                nullptr, bqkv, 1024, 1.f, 4096, 1024, 1024);

    // 3+4) fused S = softmax_one(0.125 * Q K^T), 1-MMA -> attn output
    dim3 gqs(32, BB * HH);
    qk_softmax<<<gqs, 256, SM_QS>>>(qkvHi, qkvHi + BCD, attn);

    // 5) O = P V (1-MMA), scatter to x[b, i, h*64+e], fused residual add of x1
    dim3 gpv(1, 8, BB * HH);
    kPV<<<gpv, 128, SM_1TR>>>(attn, nullptr, 1048576, 1024,
                              qkvHi + 2 * (long)BCD, nullptr, 1, 65536, 0, 64,
                              xb, nullptr, nullptr, 16, CD, 64, 1024,
                              x1, nullptr, 0, 1.f, 1024, 64, 1024);

    // 6) FFN LayerNorm -> xl single plane
    ln3_kernel<<<lng, 256>>>(xb, 1, ffnln_w, ffnln_b, nullptr, nullptr, nullptr, nullptr,
                             xlHi);

    // 7) conv1: h1 = GELU(W1 @ xl_z + b1) (1-MMA, single fp16 out)
    dim3 gc1(16, 32, BB);
    kC1<<<gc1, 128, SM_1TR>>>(c1wHi, nullptr, 0, 1024, xlHi, nullptr, 1, CD, 0, 1024,
                              nullptr, h1Hi, nullptr, 1, (long)4096 * 1024, 0, 1024,
                              nullptr, conv1_b, 0, 1.f, 4096, 1024, 1024);

    // 8) conv2 + residual: out = x + (W2 @ h1_z + b2) (1-MMA)
    dim3 gc2(16, 8, BB);
    kC2<<<gc2, 128, SM_1TR>>>(c2wHi, nullptr, 0, 4096, h1Hi, nullptr, 1, (long)4096 * 1024, 0, 1024,
                              outx, nullptr, nullptr, 1, CD, 0, 1024,
                              xb, conv2_b, 0, 1.f, 1024, 1024, 4096);
}

// round 15
// speedup vs baseline: 1.1354x; 1.0073x over previous
#include <cuda_runtime.h>
#include <cuda_fp16.h>
#include <math.h>
#include <stdint.h>

#define BB   4
#define CC   1024
#define DD   1024
#define HH   16
#define CD   (CC*DD)          // 1048576
#define BCD  (BB*CD)          // 4194304
#define H1SZ (BB*4096*1024)   // 16777216

// ---------------- scratch (static __device__ arrays; no runtime alloc) ---------------
__device__ __half g_ln_hi[3*BCD];                  // lnq/lnk/lnv single fp16 planes
__device__ __half g_qkv_hi[3*BCD];                 // q/k/v single fp16 planes
__device__ __half g_w_hi[3*CD];
__device__ __half g_c1w_hi[4*CD];
__device__ __half g_c2w_hi[4*CD];
__device__ __half g_xl_hi[BCD];
__device__ __half g_h1_hi[H1SZ];
__device__ __half g_p[64*1048576];                 // fp16 copy of attn probs
__device__ float g_x[BCD];
__device__ float g_bqkv[3*1024];

// =====================================================================================
// helpers
// =====================================================================================
__device__ __forceinline__ uint32_t smem_u32(const void* p) {
    uint32_t a;
    asm("{ .reg .u64 t; cvta.to.shared.u64 t, %1; cvt.u32.u64 %0, t; }" : "=r"(a) : "l"(p));
    return a;
}
__device__ __forceinline__ void cpa16(uint32_t s, const void* g) {
    asm volatile("cp.async.cg.shared.global [%0], [%1], 16;" :: "r"(s), "l"(g));
}
__device__ __forceinline__ void ldsm4(uint32_t addr, uint32_t& r0, uint32_t& r1,
                                      uint32_t& r2, uint32_t& r3) {
    asm volatile("ldmatrix.sync.aligned.m8n8.x4.shared.b16 {%0,%1,%2,%3}, [%4];"
                 : "=r"(r0), "=r"(r1), "=r"(r2), "=r"(r3) : "r"(addr));
}
__device__ __forceinline__ void ldsm4t(uint32_t addr, uint32_t& r0, uint32_t& r1,
                                       uint32_t& r2, uint32_t& r3) {
    asm volatile("ldmatrix.sync.aligned.m8n8.x4.trans.shared.b16 {%0,%1,%2,%3}, [%4];"
                 : "=r"(r0), "=r"(r1), "=r"(r2), "=r"(r3) : "r"(addr));
}
__device__ __forceinline__ void mma16816(float* c, const uint32_t* a, const uint32_t* b) {
    asm volatile(
        "mma.sync.aligned.m16n8k16.row.col.f32.f16.f16.f32 "
        "{%0,%1,%2,%3}, {%4,%5,%6,%7}, {%8,%9}, {%0,%1,%2,%3};"
        : "+f"(c[0]), "+f"(c[1]), "+f"(c[2]), "+f"(c[3])
        : "r"(a[0]), "r"(a[1]), "r"(a[2]), "r"(a[3]), "r"(b[0]), "r"(b[1]));
}
__device__ __forceinline__ void split1(float v, __half& h, __half& l) {
    h = __float2half_rn(v);
    l = __float2half_rn(v - __half2float(h));
}

// =====================================================================================
// Tensor-core GEMM (R11 shell): block 128x64, 4 warps, BK=32, 2-stage cp.async
// race-free, 3 CTAs/SM.
//   NMMA=1: D = a*b ; NMMA=2: D = (a_hi+a_lo)*b ; NMMA=3: + a_hi*b_lo
//   OMODE: 0 = fp32, 1 = fp16 hi/lo, 2 = fp16 single
// =====================================================================================
template<int NMMA, int OMODE, bool BTRANS, bool ACONV, bool BIAS_M, bool BIAS_N,
         bool GELUF, bool ADDF, bool SCALEF>
__global__ void __launch_bounds__(128, 3)
tc2_gemm(const void* Ahv, const __half* Alo, long strideA, int lda,
         const __half* Bhi, const __half* Blo,
         int bDiv, long bHi, long bLo, int ldb,
         float* Cf, __half* Chi, __half* Clo,
         int cDiv, long cHi, long cLo, int ldc,
         const float* Add, const float* bias, int biasZ,
         float alpha, int M, int N, int K)
{
    constexpr int BN  = 64;
    constexpr int BK  = 32;
    constexpr int SKA = 40;
    constexpr int SN  = BN + 8;
    constexpr int ASZ = 128 * SKA;
    constexpr int BSZ = BTRANS ? (BK * SN) : (BN * SKA);
    constexpr int APL = (NMMA >= 2) ? 2 : 1;
    constexpr int BPL = (NMMA == 3) ? 2 : 1;
    constexpr int STAGE = APL * ASZ + BPL * BSZ;
    constexpr int MF = 4;
    constexpr int NF = 4;

    extern __shared__ __half sm[];

    const int tid = threadIdx.x, wid = tid >> 5, lid = tid & 31;
    const int wm = wid >> 1, wn = wid & 1;
    const int z = blockIdx.z;
    const int row0 = blockIdx.y * 128, col0 = blockIdx.x * BN;

    const __half* Ahi = ACONV ? nullptr : ((const __half*)Ahv + (long)z * strideA);
    const __half* Alz = (ACONV || APL == 1) ? nullptr : (Alo + (long)z * strideA);
    const float* Af = ACONV ? ((const float*)Ahv + (long)z * strideA) : nullptr;
    Bhi += (long)(z / bDiv) * bHi + (long)(z % bDiv) * bLo;
    if (NMMA == 3) Blo += (long)(z / bDiv) * bHi + (long)(z % bDiv) * bLo;
    const long coff = (long)(z / cDiv) * cHi + (long)(z % cDiv) * cLo;
    if (BIAS_N || BIAS_M) bias += (long)z * biasZ;

    const uint32_t smBase = smem_u32(sm);
    const int nIt = K / BK;

    float acc[MF][NF][4];
#pragma unroll
    for (int i = 0; i < MF; i++)
#pragma unroll
        for (int j = 0; j < NF; j++)
#pragma unroll
            for (int r = 0; r < 4; r++) acc[i][j][r] = 0.f;

    float4 av[8];

    auto issueTile = [&](int it, int st) {
        const int k0 = it * BK;
        const uint32_t sbase = smBase + (uint32_t)(st * STAGE) * 2;
        if (!ACONV) {
#pragma unroll
            for (int pl = 0; pl < APL; pl++) {
                const __half* Ag = pl ? Alz : Ahi;
                const uint32_t sd = sbase + (uint32_t)(pl * ASZ) * 2;
#pragma unroll
                for (int i = 0; i < 4; i++) {
                    int idx = tid + (i << 7);
                    int r = idx >> 2, c8 = (idx & 3) << 3;
                    cpa16(sd + (uint32_t)(r * SKA + c8) * 2,
                          Ag + (long)(row0 + r) * lda + k0 + c8);
                }
            }
        }
        if (BTRANS) {
#pragma unroll
            for (int pl = 0; pl < BPL; pl++) {
                const __half* Bg = pl ? Blo : Bhi;
                const uint32_t sd = sbase + (uint32_t)(APL * ASZ + pl * BSZ) * 2;
#pragma unroll
                for (int i = 0; i < 2; i++) {
                    int idx = tid + (i << 7);
                    int k = idx >> 3, c8 = (idx & 7) << 3;
                    cpa16(sd + (uint32_t)(k * SN + c8) * 2,
                          Bg + (long)(k0 + k) * ldb + col0 + c8);
                }
            }
        } else {
#pragma unroll
            for (int pl = 0; pl < BPL; pl++) {
                const __half* Bg = pl ? Blo : Bhi;
                const uint32_t sd = sbase + (uint32_t)(APL * ASZ + pl * BSZ) * 2;
#pragma unroll
                for (int i = 0; i < 2; i++) {
                    int idx = tid + (i << 7);
                    int r = idx >> 2, c8 = (idx & 3) << 3;
                    cpa16(sd + (uint32_t)(r * SKA + c8) * 2,
                          Bg + (long)(col0 + r) * ldb + k0 + c8);
                }
            }
        }
    };
    auto ldgA = [&](int it) {
        const int k0 = it * BK;
#pragma unroll
        for (int i = 0; i < 8; i++) {
            int idx = tid + (i << 7);
            int r = idx >> 3, c4 = (idx & 7) << 2;
            av[i] = *(const float4*)(Af + (long)(row0 + r) * lda + k0 + c4);
        }
    };
    auto stsA = [&](int st) {
        __half* sAhi = sm + st * STAGE;
        __half* sAlo = sAhi + ASZ;
#pragma unroll
        for (int i = 0; i < 8; i++) {
            int idx = tid + (i << 7);
            int r = idx >> 3, c4 = (idx & 7) << 2;
            if (APL == 2) {
                __half h[4], l[4];
                split1(av[i].x, h[0], l[0]); split1(av[i].y, h[1], l[1]);
                split1(av[i].z, h[2], l[2]); split1(av[i].w, h[3], l[3]);
                *(uint2*)(sAhi + r * SKA + c4) = *(uint2*)h;
                *(uint2*)(sAlo + r * SKA + c4) = *(uint2*)l;
            } else {
                __half h[4] = {__float2half_rn(av[i].x), __float2half_rn(av[i].y),
                               __float2half_rn(av[i].z), __float2half_rn(av[i].w)};
                *(uint2*)(sAhi + r * SKA + c4) = *(uint2*)h;
            }
        }
    };

    if (ACONV) { ldgA(0); stsA(0); }
    issueTile(0, 0);
    asm volatile("cp.async.commit_group;");

    for (int it = 0; it < nIt; it++) {
        const int s = it & 1;
        asm volatile("cp.async.wait_group 0;");
        __syncthreads();
        if (it + 1 < nIt) {
            if (ACONV) ldgA(it + 1);
            issueTile(it + 1, s ^ 1);
            asm volatile("cp.async.commit_group;");
        }

        const uint32_t base = smBase + (uint32_t)(s * STAGE) * 2;
        const uint32_t aHiB = base, aLoB = base + ASZ * 2;
        const uint32_t bHiB = base + APL * ASZ * 2, bLoB = bHiB + BSZ * 2;

#pragma unroll
        for (int ks = 0; ks < 2; ks++) {
            uint32_t ah[MF][4], al[MF][4], bh[NF][2], bl[NF][2];
#pragma unroll
            for (int mf = 0; mf < MF; mf++) {
                uint32_t off = (uint32_t)((wm * 64 + mf * 16 + (lid & 15)) * SKA
                                          + ks * 16 + (lid >> 4) * 8) * 2;
                ldsm4(aHiB + off, ah[mf][0], ah[mf][1], ah[mf][2], ah[mf][3]);
                if (APL == 2)
                    ldsm4(aLoB + off, al[mf][0], al[mf][1], al[mf][2], al[mf][3]);
            }
            if (BTRANS) {
#pragma unroll
                for (int p = 0; p < NF / 2; p++) {
                    uint32_t off = (uint32_t)((ks * 16 + (lid & 15)) * SN
                                              + wn * 32 + p * 16 + (lid >> 4) * 8) * 2;
                    ldsm4t(bHiB + off, bh[2*p][0], bh[2*p][1], bh[2*p+1][0], bh[2*p+1][1]);
                    if (NMMA == 3)
                        ldsm4t(bLoB + off, bl[2*p][0], bl[2*p][1], bl[2*p+1][0], bl[2*p+1][1]);
                }
            } else {
#pragma unroll
                for (int p = 0; p < NF / 2; p++) {
                    uint32_t off = (uint32_t)((wn * 32 + p * 16 + (lid & 7) + (lid >> 4) * 8) * SKA
                                              + ks * 16 + ((lid >> 3) & 1) * 8) * 2;
                    ldsm4(bHiB + off, bh[2*p][0], bh[2*p][1], bh[2*p+1][0], bh[2*p+1][1]);
                    if (NMMA == 3)
                        ldsm4(bLoB + off, bl[2*p][0], bl[2*p][1], bl[2*p+1][0], bl[2*p+1][1]);
                }
            }
#pragma unroll
            for (int mf = 0; mf < MF; mf++)
#pragma unroll
                for (int nf = 0; nf < NF; nf++)
                    mma16816(acc[mf][nf], ah[mf], bh[nf]);
            if (NMMA == 3) {
#pragma unroll
                for (int mf = 0; mf < MF; mf++)
#pragma unroll
                    for (int nf = 0; nf < NF; nf++)
                        mma16816(acc[mf][nf], ah[mf], bl[nf]);
            }
            if (NMMA >= 2) {
#pragma unroll
                for (int mf = 0; mf < MF; mf++)
#pragma unroll
                    for (int nf = 0; nf < NF; nf++)
                        mma16816(acc[mf][nf], al[mf], bh[nf]);
            }
        }
        if (ACONV && it + 1 < nIt) stsA(s ^ 1);
    }

    // ---- epilogue ----
    float* Cp = (OMODE == 0) ? (Cf + coff) : nullptr;
    __half* ChP = (OMODE != 0) ? (Chi + coff) : nullptr;
    __half* ClP = (OMODE == 1) ? (Clo + coff) : nullptr;
    const float* Ap2 = ADDF ? (Add + coff) : nullptr;
    const int rBase = row0 + wm * 64 + (lid >> 2);
    const int cBase = col0 + wn * 32 + (lid & 3) * 2;
#pragma unroll
    for (int mf = 0; mf < MF; mf++) {
#pragma unroll
        for (int half = 0; half < 2; half++) {
            const int gr = rBase + mf * 16 + half * 8;
            const float bm = BIAS_M ? bias[gr] : 0.f;
#pragma unroll
            for (int nf = 0; nf < NF; nf++) {
                const int gc = cBase + nf * 8;
                float v0 = acc[mf][nf][half * 2 + 0];
                float v1 = acc[mf][nf][half * 2 + 1];
                if (SCALEF) { v0 *= alpha; v1 *= alpha; }
                if (BIAS_M) { v0 += bm; v1 += bm; }
                if (BIAS_N) { v0 += bias[gc]; v1 += bias[gc + 1]; }
                if (GELUF) {
                    v0 = 0.5f * v0 * (1.0f + erff(v0 * 0.70710678118654752f));
                    v1 = 0.5f * v1 * (1.0f + erff(v1 * 0.70710678118654752f));
                }
                long off = (long)gr * ldc + gc;
                if (ADDF) { v0 += Ap2[off]; v1 += Ap2[off + 1]; }
                if (OMODE == 1) {
                    __half h0, l0, h1, l1;
                    split1(v0, h0, l0); split1(v1, h1, l1);
                    __half hp[2] = {h0, h1}, lp[2] = {l0, l1};
                    *(uint32_t*)(ChP + off) = *(uint32_t*)hp;
                    *(uint32_t*)(ClP + off) = *(uint32_t*)lp;
                } else if (OMODE == 2) {
                    __half hp[2] = {__float2half_rn(v0), __float2half_rn(v1)};
                    *(uint32_t*)(ChP + off) = *(uint32_t*)hp;
                } else {
                    *(float2*)(Cp + off) = make_float2(v0, v1);
                }
            }
        }
    }
}

// =====================================================================================
// Fused QK^T * 0.125 + softmax-one. Writes fp32 attn (streaming .cs, never re-read)
// AND fp16 P copy for the PV GEMM. Single-plane q/k, 1-MMA.
// =====================================================================================
__global__ void __launch_bounds__(256, 1)
qk_softmax(const __half* __restrict__ qH, const __half* __restrict__ kH,
           float* __restrict__ attn, __half* __restrict__ pOut)
{
    constexpr int SK = 72;
    constexpr int QPL = 32 * SK;
    constexpr int KPL = 128 * SK;
    extern __shared__ __half sm[];
    float* redA = (float*)(sm + QPL + 2 * KPL);
    float* redB = redA + 32 * 9;

    const int tid = threadIdx.x, wid = tid >> 5, lid = tid & 31;
    const int z = blockIdx.y;
    const int row0 = blockIdx.x * 32;
    const __half* Qh = qH + (long)z * 65536;
    const __half* Kh = kH + (long)z * 65536;
    attn += (long)z * 1048576;
    pOut += (long)z * 1048576;

    const uint32_t smBase = smem_u32(sm);

    {
        int r = tid >> 3, c8 = (tid & 7) << 3;
        cpa16(smBase + (uint32_t)(r * SK + c8) * 2, Qh + (long)(row0 + r) * 64 + c8);
    }
    auto issueK = [&](int ch, int st) {
        const uint32_t sd = smBase + (uint32_t)(QPL + st * KPL) * 2;
#pragma unroll
        for (int i = 0; i < 4; i++) {
            int idx = tid + (i << 8);
            int r = idx >> 3, c8 = (idx & 7) << 3;
            cpa16(sd + (uint32_t)(r * SK + c8) * 2,
                  Kh + (long)(ch * 128 + r) * 64 + c8);
        }
    };
    issueK(0, 0);
    asm volatile("cp.async.commit_group;");

    float acc[2][8][2][4];
#pragma unroll
    for (int mf = 0; mf < 2; mf++)
#pragma unroll
        for (int ch = 0; ch < 8; ch++)
#pragma unroll
            for (int nf = 0; nf < 2; nf++)
#pragma unroll
                for (int r = 0; r < 4; r++) acc[mf][ch][nf][r] = 0.f;

    uint32_t aH[4][2][4];

    for (int ch = 0; ch < 8; ch++) {
        asm volatile("cp.async.wait_group 0;");
        __syncthreads();
        if (ch + 1 < 8) {
            issueK(ch + 1, (ch + 1) & 1);
            asm volatile("cp.async.commit_group;");
        }
        if (ch == 0) {
#pragma unroll
            for (int ks = 0; ks < 4; ks++)
#pragma unroll
                for (int mf = 0; mf < 2; mf++) {
                    uint32_t off = (uint32_t)((mf * 16 + (lid & 15)) * SK
                                              + ks * 16 + (lid >> 4) * 8) * 2;
                    ldsm4(smBase + off, aH[ks][mf][0], aH[ks][mf][1],
                                        aH[ks][mf][2], aH[ks][mf][3]);
                }
        }
        const uint32_t kB = smBase + (uint32_t)(QPL + (ch & 1) * KPL) * 2;
#pragma unroll
        for (int ks = 0; ks < 4; ks++) {
            uint32_t bh[2][2];
            uint32_t off = (uint32_t)((wid * 16 + (lid & 7) + (lid >> 4) * 8) * SK
                                      + ks * 16 + ((lid >> 3) & 1) * 8) * 2;
            ldsm4(kB + off, bh[0][0], bh[0][1], bh[1][0], bh[1][1]);
#pragma unroll
            for (int mf = 0; mf < 2; mf++)
#pragma unroll
                for (int nf = 0; nf < 2; nf++)
                    mma16816(acc[mf][ch][nf], aH[ks][mf], bh[nf]);
        }
    }

    // ---- softmax-one ----
    const int rq = lid >> 2, cq = lid & 3;
#pragma unroll
    for (int mf = 0; mf < 2; mf++)
#pragma unroll
        for (int ch = 0; ch < 8; ch++)
#pragma unroll
            for (int nf = 0; nf < 2; nf++)
#pragma unroll
                for (int r = 0; r < 4; r++) acc[mf][ch][nf][r] *= 0.125f;

    float mx[2][2];
#pragma unroll
    for (int mf = 0; mf < 2; mf++)
#pragma unroll
        for (int half = 0; half < 2; half++) {
            float m = -1e30f;
#pragma unroll
            for (int ch = 0; ch < 8; ch++)
#pragma unroll
                for (int nf = 0; nf < 2; nf++)
                    m = fmaxf(m, fmaxf(acc[mf][ch][nf][half*2], acc[mf][ch][nf][half*2+1]));
            m = fmaxf(m, __shfl_xor_sync(0xffffffffu, m, 1));
            m = fmaxf(m, __shfl_xor_sync(0xffffffffu, m, 2));
            mx[mf][half] = m;
        }
    if (cq == 0) {
#pragma unroll
        for (int mf = 0; mf < 2; mf++)
#pragma unroll
            for (int half = 0; half < 2; half++)
                redA[(mf * 16 + half * 8 + rq) * 9 + wid] = mx[mf][half];
    }
    __syncthreads();
#pragma unroll
    for (int mf = 0; mf < 2; mf++)
#pragma unroll
        for (int half = 0; half < 2; half++) {
            float m = -1e30f;
            const float* rr = redA + (mf * 16 + half * 8 + rq) * 9;
#pragma unroll
            for (int w = 0; w < 8; w++) m = fmaxf(m, rr[w]);
            mx[mf][half] = m;
        }

    float sum[2][2] = {{0.f, 0.f}, {0.f, 0.f}};
#pragma unroll
    for (int mf = 0; mf < 2; mf++)
#pragma unroll
        for (int half = 0; half < 2; half++) {
            const float m = mx[mf][half];
            float s = 0.f;
#pragma unroll
            for (int ch = 0; ch < 8; ch++)
#pragma unroll
                for (int nf = 0; nf < 2; nf++) {
                    float e0 = __expf(acc[mf][ch][nf][half*2]     - m);
                    float e1 = __expf(acc[mf][ch][nf][half*2 + 1] - m);
                    acc[mf][ch][nf][half*2]     = e0;
                    acc[mf][ch][nf][half*2 + 1] = e1;
                    s += e0 + e1;
                }
            s += __shfl_xor_sync(0xffffffffu, s, 1);
            s += __shfl_xor_sync(0xffffffffu, s, 2);
            sum[mf][half] = s;
        }
    if (cq == 0) {
#pragma unroll
        for (int mf = 0; mf < 2; mf++)
#pragma unroll
            for (int half = 0; half < 2; half++)
                redB[(mf * 16 + half * 8 + rq) * 9 + wid] = sum[mf][half];
    }
    __syncthreads();
#pragma unroll
    for (int mf = 0; mf < 2; mf++)
#pragma unroll
        for (int half = 0; half < 2; half++) {
            float s = 0.f;
            const float* rr = redB + (mf * 16 + half * 8 + rq) * 9;
#pragma unroll
            for (int w = 0; w < 8; w++) s += rr[w];
            sum[mf][half] = 1.0f / (1.0f + s);
        }

    // ---- write normalized P: fp32 (streaming, output) + fp16 copy for PV ----
#pragma unroll
    for (int mf = 0; mf < 2; mf++)
#pragma unroll
        for (int half = 0; half < 2; half++) {
            const int gr = row0 + mf * 16 + half * 8 + rq;
            const float inv = sum[mf][half];
#pragma unroll
            for (int ch = 0; ch < 8; ch++)
#pragma unroll
                for (int nf = 0; nf < 2; nf++) {
                    const int gc = ch * 128 + wid * 16 + nf * 8 + cq * 2;
                    float p0 = acc[mf][ch][nf][half*2]     * inv;
                    float p1 = acc[mf][ch][nf][half*2 + 1] * inv;
                    __stcs((float2*)(attn + (long)gr * 1024 + gc), make_float2(p0, p1));
                    __half2 ph = __floats2half2_rn(p0, p1);
                    *(uint32_t*)(pOut + (long)gr * 1024 + gc) = *(uint32_t*)&ph;
                }
        }
}

// =====================================================================================
__global__ void cvt_hi(const float* __restrict__ s, __half* __restrict__ hi, int n4)
{
    int i = blockIdx.x * 256 + threadIdx.x;
    if (i >= n4) return;
    float4 v = ((const float4*)s)[i];
    __half h[4] = {__float2half_rn(v.x), __float2half_rn(v.y),
                   __float2half_rn(v.z), __float2half_rn(v.w)};
    ((uint2*)hi)[i] = *(uint2*)h;
}

// convert 3 equal-size fp32 matrices into consecutive fp16 planes (one launch)
__global__ void cvt3_hi(const float* __restrict__ a, const float* __restrict__ b,
                        const float* __restrict__ c, __half* __restrict__ o, int n4)
{
    int i = blockIdx.x * 256 + threadIdx.x;
    if (i >= n4) return;
    const float* srcs[3] = {a, b, c};
#pragma unroll
    for (int p = 0; p < 3; p++) {
        float4 v = ((const float4*)srcs[p])[i];
        __half h[4] = {__float2half_rn(v.x), __float2half_rn(v.y),
                       __float2half_rn(v.z), __float2half_rn(v.w)};
        ((uint2*)(o + (long)p * CD))[i] = *(uint2*)h;
    }
}

__global__ void bias_gather(const float* a, const float* b, const float* c, float* o)
{
    const float* src[3] = {a, b, c};
    o[blockIdx.x * 1024 + threadIdx.x] = src[blockIdx.x][threadIdx.x];
}

// =====================================================================================
// channel LayerNorm -> fp16 single planes (up to 3)
// =====================================================================================
__global__ void ln3_kernel(const float* __restrict__ x, int nOut,
    const float* __restrict__ w0, const float* __restrict__ b0,
    const float* __restrict__ w1, const float* __restrict__ b1,
    const float* __restrict__ w2, const float* __restrict__ b2,
    __half* __restrict__ oHi)
{
    const int dx   = threadIdx.x & 31;
    const int lane = threadIdx.x >> 5;
    const int d    = blockIdx.x * 32 + dx;
    const long base = (long)blockIdx.y * CD + d;

    float s = 0.f, ss = 0.f;
    for (int c = lane; c < CC; c += 8) {
        float v = x[base + (long)c * DD];
        s += v; ss += v * v;
    }
    __shared__ float sS[8][33], sQ[8][33];
    sS[lane][dx] = s; sQ[lane][dx] = ss;
    __syncthreads();
    if (lane == 0) {
        float ts = 0.f, tq = 0.f;
        #pragma unroll
        for (int i = 0; i < 8; i++) { ts += sS[i][dx]; tq += sQ[i][dx]; }
        float mean = ts * (1.0f / CC);
        float var  = tq * (1.0f / CC) - mean * mean;
        sS[0][dx] = mean;
        sQ[0][dx] = rsqrtf(var + 1e-6f);
    }
    __syncthreads();
    const float mean = sS[0][dx];
    const float rstd = sQ[0][dx];
    const float* W[3] = {w0, w1, w2};
    const float* Bv[3] = {b0, b1, b2};
    for (int c = lane; c < CC; c += 8) {
        long idx = base + (long)c * DD;
        float xn = (x[idx] - mean) * rstd;
        for (int p = 0; p < nOut; p++)
            oHi[(long)p * BCD + idx] = __float2half_rn(W[p][c] * xn + Bv[p][c]);
    }
}

// =====================================================================================
extern "C" void kernel_launch(void* const* d_in, const int* in_sizes, int n_in,
                              void* d_out, int out_size)
{
    const float* x1      = (const float*)d_in[0];
    const float* lnq_w   = (const float*)d_in[1];
    const float* lnq_b   = (const float*)d_in[2];
    const float* lnk_w   = (const float*)d_in[3];
    const float* lnk_b   = (const float*)d_in[4];
    const float* lnv_w   = (const float*)d_in[5];
    const float* lnv_b   = (const float*)d_in[6];
    const float* wq      = (const float*)d_in[7];
    const float* bq      = (const float*)d_in[8];
    const float* wk      = (const float*)d_in[9];
    const float* bk      = (const float*)d_in[10];
    const float* wv      = (const float*)d_in[11];
    const float* bv      = (const float*)d_in[12];
    const float* ffnln_w = (const float*)d_in[13];
    const float* ffnln_b = (const float*)d_in[14];
    const float* conv1_w = (const float*)d_in[15];
    const float* conv1_b = (const float*)d_in[16];
    const float* conv2_w = (const float*)d_in[17];
    const float* conv2_b = (const float*)d_in[18];

    __half *lnHi, *qkvHi, *wHi;
    __half *c1wHi, *c2wHi, *xlHi, *h1Hi, *pBuf;
    float *xb, *bqkv;
    cudaGetSymbolAddress((void**)&lnHi,  g_ln_hi);
    cudaGetSymbolAddress((void**)&qkvHi, g_qkv_hi);
    cudaGetSymbolAddress((void**)&wHi,   g_w_hi);
    cudaGetSymbolAddress((void**)&c1wHi, g_c1w_hi);
    cudaGetSymbolAddress((void**)&c2wHi, g_c2w_hi);
    cudaGetSymbolAddress((void**)&xlHi,  g_xl_hi);
    cudaGetSymbolAddress((void**)&h1Hi,  g_h1_hi);
    cudaGetSymbolAddress((void**)&pBuf,  g_p);
    cudaGetSymbolAddress((void**)&xb,    g_x);
    cudaGetSymbolAddress((void**)&bqkv,  g_bqkv);

    float* outx = (float*)d_out;
    float* attn = outx + (long)BCD;

    // all-single-fp16 plan; PV now consumes fp16 P via standard cp.async pipeline
    auto kQKV = tc2_gemm<1, 2, false, false, false, true,  false, false, false>;
    auto kPV  = tc2_gemm<1, 0, true,  false, false, false, false, true,  false>;
    auto kC1  = tc2_gemm<1, 2, true,  false, true,  false, true,  false, false>;
    auto kC2  = tc2_gemm<1, 0, true,  false, true,  false, false, true,  false>;
    const int SM_1KB = 2 * (1 * 128 * 40 + 1 * 64 * 40) * 2;  // 30720 (QKV)
    const int SM_1TR = 2 * (1 * 128 * 40 + 1 * 32 * 72) * 2;  // 29696 (PV/C1/C2)
    const int SM_QS  = (32 * 72 + 2 * 128 * 72) * 2 + 2 * 32 * 9 * 4;  // 43776
    cudaFuncSetAttribute(kQKV, cudaFuncAttributeMaxDynamicSharedMemorySize, SM_1KB);
    cudaFuncSetAttribute(kPV,  cudaFuncAttributeMaxDynamicSharedMemorySize, SM_1TR);
    cudaFuncSetAttribute(kC1,  cudaFuncAttributeMaxDynamicSharedMemorySize, SM_1TR);
    cudaFuncSetAttribute(kC2,  cudaFuncAttributeMaxDynamicSharedMemorySize, SM_1TR);
    cudaFuncSetAttribute(qk_softmax, cudaFuncAttributeMaxDynamicSharedMemorySize, SM_QS);

    // launch order arranged so launch #5 (ncu -s 5 -c 1) = qk_softmax
    // [0] qkv weight converts (fused)
    cvt3_hi<<<CD / 4 / 256, 256>>>(wq, wk, wv, wHi, CD / 4);
    // [1] biases
    bias_gather<<<3, 1024>>>(bq, bk, bv, bqkv);
    // [2] QKV LayerNorms -> single fp16 planes
    dim3 lng(DD / 32, BB);
    ln3_kernel<<<lng, 256>>>(x1, 3, lnq_w, lnq_b, lnk_w, lnk_b, lnv_w, lnv_b, lnHi);
    // [3] fused QKV linears
    dim3 gqkv(16, 32, 3);
    kQKV<<<gqkv, 128, SM_1KB>>>(lnHi, nullptr, BCD, 1024, wHi, nullptr, 1, CD, 0, 1024,
                                nullptr, qkvHi, nullptr, 1, BCD, 0, 1024,
                                nullptr, bqkv, 1024, 1.f, 4096, 1024, 1024);
    // [4] conv1 weight convert (independent; placed here for ncu alignment)
    cvt_hi<<<4 * CD / 4 / 256, 256>>>(conv1_w, c1wHi, 4 * CD / 4);
    // [5] fused QK softmax-one -> attn (fp32 .cs) + P (fp16)   <- ncu capture
    dim3 gqs(32, BB * HH);
    qk_softmax<<<gqs, 256, SM_QS>>>(qkvHi, qkvHi + BCD, attn, pBuf);
    // [6] O = P V, scatter + x1 residual -> g_x
    dim3 gpv(1, 8, BB * HH);
    kPV<<<gpv, 128, SM_1TR>>>(pBuf, nullptr, 1048576, 1024,
                              qkvHi + 2 * (long)BCD, nullptr, 1, 65536, 0, 64,
                              xb, nullptr, nullptr, 16, CD, 64, 1024,
                              x1, nullptr, 0, 1.f, 1024, 64, 1024);
    // [7] FFN LayerNorm -> xl
    ln3_kernel<<<lng, 256>>>(xb, 1, ffnln_w, ffnln_b, nullptr, nullptr, nullptr, nullptr,
                             xlHi);
    // [8] conv2 weight convert
    cvt_hi<<<4 * CD / 4 / 256, 256>>>(conv2_w, c2wHi, 4 * CD / 4);
    // [9] conv1: h1 = GELU(W1 @ xl_z + b1)
    dim3 gc1(16, 32, BB);
    kC1<<<gc1, 128, SM_1TR>>>(c1wHi, nullptr, 0, 1024, xlHi, nullptr, 1, CD, 0, 1024,
                              nullptr, h1Hi, nullptr, 1, (long)4096 * 1024, 0, 1024,
                              nullptr, conv1_b, 0, 1.f, 4096, 1024, 1024);
    // [10] conv2 + residual
    dim3 gc2(16, 8, BB);
    kC2<<<gc2, 128, SM_1TR>>>(c2wHi, nullptr, 0, 4096, h1Hi, nullptr, 1, (long)4096 * 1024, 0, 1024,
                              outx, nullptr, nullptr, 1, CD, 0, 1024,
                              xb, conv2_b, 0, 1.f, 1024, 1024, 4096);
}

// round 16
// speedup vs baseline: 1.2576x; 1.1076x over previous
#include <cuda_runtime.h>
#include <cuda_fp16.h>
#include <math.h>
#include <stdint.h>

#define BB   4
#define CC   1024
#define DD   1024
#define HH   16
#define CD   (CC*DD)          // 1048576
#define BCD  (BB*CD)          // 4194304
#define H1SZ (BB*4096*1024)   // 16777216

// ---------------- scratch (static __device__ arrays; no runtime alloc) ---------------
__device__ __half g_ln_hi[3*BCD];                  // lnq/lnk/lnv single fp16 planes
__device__ __half g_qkv_hi[3*BCD];                 // q/k/v single fp16 planes
__device__ __half g_w_hi[3*CD];
__device__ __half g_c1w_hi[4*CD];
__device__ __half g_c2w_hi[4*CD];
__device__ __half g_xl_hi[BCD];
__device__ __half g_h1_hi[H1SZ];
__device__ __half g_p[64*1048576];                 // fp16 copy of attn probs
__device__ float g_x[BCD];
__device__ float g_bqkv[3*1024];

// =====================================================================================
// helpers
// =====================================================================================
__device__ __forceinline__ uint32_t smem_u32(const void* p) {
    uint32_t a;
    asm("{ .reg .u64 t; cvta.to.shared.u64 t, %1; cvt.u32.u64 %0, t; }" : "=r"(a) : "l"(p));
    return a;
}
__device__ __forceinline__ void cpa16(uint32_t s, const void* g) {
    asm volatile("cp.async.cg.shared.global [%0], [%1], 16;" :: "r"(s), "l"(g));
}
__device__ __forceinline__ void ldsm4(uint32_t addr, uint32_t& r0, uint32_t& r1,
                                      uint32_t& r2, uint32_t& r3) {
    asm volatile("ldmatrix.sync.aligned.m8n8.x4.shared.b16 {%0,%1,%2,%3}, [%4];"
                 : "=r"(r0), "=r"(r1), "=r"(r2), "=r"(r3) : "r"(addr));
}
__device__ __forceinline__ void ldsm4t(uint32_t addr, uint32_t& r0, uint32_t& r1,
                                       uint32_t& r2, uint32_t& r3) {
    asm volatile("ldmatrix.sync.aligned.m8n8.x4.trans.shared.b16 {%0,%1,%2,%3}, [%4];"
                 : "=r"(r0), "=r"(r1), "=r"(r2), "=r"(r3) : "r"(addr));
}
__device__ __forceinline__ void mma16816(float* c, const uint32_t* a, const uint32_t* b) {
    asm volatile(
        "mma.sync.aligned.m16n8k16.row.col.f32.f16.f16.f32 "
        "{%0,%1,%2,%3}, {%4,%5,%6,%7}, {%8,%9}, {%0,%1,%2,%3};"
        : "+f"(c[0]), "+f"(c[1]), "+f"(c[2]), "+f"(c[3])
        : "r"(a[0]), "r"(a[1]), "r"(a[2]), "r"(a[3]), "r"(b[0]), "r"(b[1]));
}
__device__ __forceinline__ void split1(float v, __half& h, __half& l) {
    h = __float2half_rn(v);
    l = __float2half_rn(v - __half2float(h));
}

// =====================================================================================
// Tensor-core GEMM: block 128x64, 4 warps, BK=32, 2-stage cp.async race-free,
// 4 CTAs/SM (128-reg cap; 1-MMA config fits without spills).
//   NMMA=1: D = a*b ; NMMA=2: D = (a_hi+a_lo)*b ; NMMA=3: + a_hi*b_lo
//   OMODE: 0 = fp32, 1 = fp16 hi/lo, 2 = fp16 single
// =====================================================================================
template<int NMMA, int OMODE, bool BTRANS, bool ACONV, bool BIAS_M, bool BIAS_N,
         bool GELUF, bool ADDF, bool SCALEF>
__global__ void __launch_bounds__(128, 4)
tc2_gemm(const void* Ahv, const __half* Alo, long strideA, int lda,
         const __half* Bhi, const __half* Blo,
         int bDiv, long bHi, long bLo, int ldb,
         float* Cf, __half* Chi, __half* Clo,
         int cDiv, long cHi, long cLo, int ldc,
         const float* Add, const float* bias, int biasZ,
         float alpha, int M, int N, int K)
{
    constexpr int BN  = 64;
    constexpr int BK  = 32;
    constexpr int SKA = 40;
    constexpr int SN  = BN + 8;
    constexpr int ASZ = 128 * SKA;
    constexpr int BSZ = BTRANS ? (BK * SN) : (BN * SKA);
    constexpr int APL = (NMMA >= 2) ? 2 : 1;
    constexpr int BPL = (NMMA == 3) ? 2 : 1;
    constexpr int STAGE = APL * ASZ + BPL * BSZ;
    constexpr int MF = 4;
    constexpr int NF = 4;

    extern __shared__ __half sm[];

    const int tid = threadIdx.x, wid = tid >> 5, lid = tid & 31;
    const int wm = wid >> 1, wn = wid & 1;
    const int z = blockIdx.z;
    const int row0 = blockIdx.y * 128, col0 = blockIdx.x * BN;

    const __half* Ahi = ACONV ? nullptr : ((const __half*)Ahv + (long)z * strideA);
    const __half* Alz = (ACONV || APL == 1) ? nullptr : (Alo + (long)z * strideA);
    const float* Af = ACONV ? ((const float*)Ahv + (long)z * strideA) : nullptr;
    Bhi += (long)(z / bDiv) * bHi + (long)(z % bDiv) * bLo;
    if (NMMA == 3) Blo += (long)(z / bDiv) * bHi + (long)(z % bDiv) * bLo;
    const long coff = (long)(z / cDiv) * cHi + (long)(z % cDiv) * cLo;
    if (BIAS_N || BIAS_M) bias += (long)z * biasZ;

    const uint32_t smBase = smem_u32(sm);
    const int nIt = K / BK;

    float acc[MF][NF][4];
#pragma unroll
    for (int i = 0; i < MF; i++)
#pragma unroll
        for (int j = 0; j < NF; j++)
#pragma unroll
            for (int r = 0; r < 4; r++) acc[i][j][r] = 0.f;

    float4 av[8];

    auto issueTile = [&](int it, int st) {
        const int k0 = it * BK;
        const uint32_t sbase = smBase + (uint32_t)(st * STAGE) * 2;
        if (!ACONV) {
#pragma unroll
            for (int pl = 0; pl < APL; pl++) {
                const __half* Ag = pl ? Alz : Ahi;
                const uint32_t sd = sbase + (uint32_t)(pl * ASZ) * 2;
#pragma unroll
                for (int i = 0; i < 4; i++) {
                    int idx = tid + (i << 7);
                    int r = idx >> 2, c8 = (idx & 3) << 3;
                    cpa16(sd + (uint32_t)(r * SKA + c8) * 2,
                          Ag + (long)(row0 + r) * lda + k0 + c8);
                }
            }
        }
        if (BTRANS) {
#pragma unroll
            for (int pl = 0; pl < BPL; pl++) {
                const __half* Bg = pl ? Blo : Bhi;
                const uint32_t sd = sbase + (uint32_t)(APL * ASZ + pl * BSZ) * 2;
#pragma unroll
                for (int i = 0; i < 2; i++) {
                    int idx = tid + (i << 7);
                    int k = idx >> 3, c8 = (idx & 7) << 3;
                    cpa16(sd + (uint32_t)(k * SN + c8) * 2,
                          Bg + (long)(k0 + k) * ldb + col0 + c8);
                }
            }
        } else {
#pragma unroll
            for (int pl = 0; pl < BPL; pl++) {
                const __half* Bg = pl ? Blo : Bhi;
                const uint32_t sd = sbase + (uint32_t)(APL * ASZ + pl * BSZ) * 2;
#pragma unroll
                for (int i = 0; i < 2; i++) {
                    int idx = tid + (i << 7);
                    int r = idx >> 2, c8 = (idx & 3) << 3;
                    cpa16(sd + (uint32_t)(r * SKA + c8) * 2,
                          Bg + (long)(col0 + r) * ldb + k0 + c8);
                }
            }
        }
    };
    auto ldgA = [&](int it) {
        const int k0 = it * BK;
#pragma unroll
        for (int i = 0; i < 8; i++) {
            int idx = tid + (i << 7);
            int r = idx >> 3, c4 = (idx & 7) << 2;
            av[i] = *(const float4*)(Af + (long)(row0 + r) * lda + k0 + c4);
        }
    };
    auto stsA = [&](int st) {
        __half* sAhi = sm + st * STAGE;
        __half* sAlo = sAhi + ASZ;
#pragma unroll
        for (int i = 0; i < 8; i++) {
            int idx = tid + (i << 7);
            int r = idx >> 3, c4 = (idx & 7) << 2;
            if (APL == 2) {
                __half h[4], l[4];
                split1(av[i].x, h[0], l[0]); split1(av[i].y, h[1], l[1]);
                split1(av[i].z, h[2], l[2]); split1(av[i].w, h[3], l[3]);
                *(uint2*)(sAhi + r * SKA + c4) = *(uint2*)h;
                *(uint2*)(sAlo + r * SKA + c4) = *(uint2*)l;
            } else {
                __half h[4] = {__float2half_rn(av[i].x), __float2half_rn(av[i].y),
                               __float2half_rn(av[i].z), __float2half_rn(av[i].w)};
                *(uint2*)(sAhi + r * SKA + c4) = *(uint2*)h;
            }
        }
    };

    if (ACONV) { ldgA(0); stsA(0); }
    issueTile(0, 0);
    asm volatile("cp.async.commit_group;");

    for (int it = 0; it < nIt; it++) {
        const int s = it & 1;
        asm volatile("cp.async.wait_group 0;");
        __syncthreads();
        if (it + 1 < nIt) {
            if (ACONV) ldgA(it + 1);
            issueTile(it + 1, s ^ 1);
            asm volatile("cp.async.commit_group;");
        }

        const uint32_t base = smBase + (uint32_t)(s * STAGE) * 2;
        const uint32_t aHiB = base, aLoB = base + ASZ * 2;
        const uint32_t bHiB = base + APL * ASZ * 2, bLoB = bHiB + BSZ * 2;

#pragma unroll
        for (int ks = 0; ks < 2; ks++) {
            uint32_t ah[MF][4], al[MF][4], bh[NF][2], bl[NF][2];
#pragma unroll
            for (int mf = 0; mf < MF; mf++) {
                uint32_t off = (uint32_t)((wm * 64 + mf * 16 + (lid & 15)) * SKA
                                          + ks * 16 + (lid >> 4) * 8) * 2;
                ldsm4(aHiB + off, ah[mf][0], ah[mf][1], ah[mf][2], ah[mf][3]);
                if (APL == 2)
                    ldsm4(aLoB + off, al[mf][0], al[mf][1], al[mf][2], al[mf][3]);
            }
            if (BTRANS) {
#pragma unroll
                for (int p = 0; p < NF / 2; p++) {
                    uint32_t off = (uint32_t)((ks * 16 + (lid & 15)) * SN
                                              + wn * 32 + p * 16 + (lid >> 4) * 8) * 2;
                    ldsm4t(bHiB + off, bh[2*p][0], bh[2*p][1], bh[2*p+1][0], bh[2*p+1][1]);
                    if (NMMA == 3)
                        ldsm4t(bLoB + off, bl[2*p][0], bl[2*p][1], bl[2*p+1][0], bl[2*p+1][1]);
                }
            } else {
#pragma unroll
                for (int p = 0; p < NF / 2; p++) {
                    uint32_t off = (uint32_t)((wn * 32 + p * 16 + (lid & 7) + (lid >> 4) * 8) * SKA
                                              + ks * 16 + ((lid >> 3) & 1) * 8) * 2;
                    ldsm4(bHiB + off, bh[2*p][0], bh[2*p][1], bh[2*p+1][0], bh[2*p+1][1]);
                    if (NMMA == 3)
                        ldsm4(bLoB + off, bl[2*p][0], bl[2*p][1], bl[2*p+1][0], bl[2*p+1][1]);
                }
            }
#pragma unroll
            for (int mf = 0; mf < MF; mf++)
#pragma unroll
                for (int nf = 0; nf < NF; nf++)
                    mma16816(acc[mf][nf], ah[mf], bh[nf]);
            if (NMMA == 3) {
#pragma unroll
                for (int mf = 0; mf < MF; mf++)
#pragma unroll
                    for (int nf = 0; nf < NF; nf++)
                        mma16816(acc[mf][nf], ah[mf], bl[nf]);
            }
            if (NMMA >= 2) {
#pragma unroll
                for (int mf = 0; mf < MF; mf++)
#pragma unroll
                    for (int nf = 0; nf < NF; nf++)
                        mma16816(acc[mf][nf], al[mf], bh[nf]);
            }
        }
        if (ACONV && it + 1 < nIt) stsA(s ^ 1);
    }

    // ---- epilogue ----
    float* Cp = (OMODE == 0) ? (Cf + coff) : nullptr;
    __half* ChP = (OMODE != 0) ? (Chi + coff) : nullptr;
    __half* ClP = (OMODE == 1) ? (Clo + coff) : nullptr;
    const float* Ap2 = ADDF ? (Add + coff) : nullptr;
    const int rBase = row0 + wm * 64 + (lid >> 2);
    const int cBase = col0 + wn * 32 + (lid & 3) * 2;
#pragma unroll
    for (int mf = 0; mf < MF; mf++) {
#pragma unroll
        for (int half = 0; half < 2; half++) {
            const int gr = rBase + mf * 16 + half * 8;
            const float bm = BIAS_M ? bias[gr] : 0.f;
#pragma unroll
            for (int nf = 0; nf < NF; nf++) {
                const int gc = cBase + nf * 8;
                float v0 = acc[mf][nf][half * 2 + 0];
                float v1 = acc[mf][nf][half * 2 + 1];
                if (SCALEF) { v0 *= alpha; v1 *= alpha; }
                if (BIAS_M) { v0 += bm; v1 += bm; }
                if (BIAS_N) { v0 += bias[gc]; v1 += bias[gc + 1]; }
                if (GELUF) {
                    v0 = 0.5f * v0 * (1.0f + erff(v0 * 0.70710678118654752f));
                    v1 = 0.5f * v1 * (1.0f + erff(v1 * 0.70710678118654752f));
                }
                long off = (long)gr * ldc + gc;
                if (ADDF) { v0 += Ap2[off]; v1 += Ap2[off + 1]; }
                if (OMODE == 1) {
                    __half h0, l0, h1, l1;
                    split1(v0, h0, l0); split1(v1, h1, l1);
                    __half hp[2] = {h0, h1}, lp[2] = {l0, l1};
                    *(uint32_t*)(ChP + off) = *(uint32_t*)hp;
                    *(uint32_t*)(ClP + off) = *(uint32_t*)lp;
                } else if (OMODE == 2) {
                    __half hp[2] = {__float2half_rn(v0), __float2half_rn(v1)};
                    *(uint32_t*)(ChP + off) = *(uint32_t*)hp;
                } else {
                    *(float2*)(Cp + off) = make_float2(v0, v1);
                }
            }
        }
    }
}

// =====================================================================================
// Fused QK^T * 0.125 + softmax-one. Writes fp32 attn (streaming .cs, never re-read)
// AND fp16 P copy for the PV GEMM. Single-plane q/k, 1-MMA.
// =====================================================================================
__global__ void __launch_bounds__(256, 1)
qk_softmax(const __half* __restrict__ qH, const __half* __restrict__ kH,
           float* __restrict__ attn, __half* __restrict__ pOut)
{
    constexpr int SK = 72;
    constexpr int QPL = 32 * SK;
    constexpr int KPL = 128 * SK;
    extern __shared__ __half sm[];
    float* redA = (float*)(sm + QPL + 2 * KPL);
    float* redB = redA + 32 * 9;

    const int tid = threadIdx.x, wid = tid >> 5, lid = tid & 31;
    const int z = blockIdx.y;
    const int row0 = blockIdx.x * 32;
    const __half* Qh = qH + (long)z * 65536;
    const __half* Kh = kH + (long)z * 65536;
    attn += (long)z * 1048576;
    pOut += (long)z * 1048576;

    const uint32_t smBase = smem_u32(sm);

    {
        int r = tid >> 3, c8 = (tid & 7) << 3;
        cpa16(smBase + (uint32_t)(r * SK + c8) * 2, Qh + (long)(row0 + r) * 64 + c8);
    }
    auto issueK = [&](int ch, int st) {
        const uint32_t sd = smBase + (uint32_t)(QPL + st * KPL) * 2;
#pragma unroll
        for (int i = 0; i < 4; i++) {
            int idx = tid + (i << 8);
            int r = idx >> 3, c8 = (idx & 7) << 3;
            cpa16(sd + (uint32_t)(r * SK + c8) * 2,
                  Kh + (long)(ch * 128 + r) * 64 + c8);
        }
    };
    issueK(0, 0);
    asm volatile("cp.async.commit_group;");

    float acc[2][8][2][4];
#pragma unroll
    for (int mf = 0; mf < 2; mf++)
#pragma unroll
        for (int ch = 0; ch < 8; ch++)
#pragma unroll
            for (int nf = 0; nf < 2; nf++)
#pragma unroll
                for (int r = 0; r < 4; r++) acc[mf][ch][nf][r] = 0.f;

    uint32_t aH[4][2][4];

    for (int ch = 0; ch < 8; ch++) {
        asm volatile("cp.async.wait_group 0;");
        __syncthreads();
        if (ch + 1 < 8) {
            issueK(ch + 1, (ch + 1) & 1);
            asm volatile("cp.async.commit_group;");
        }
        if (ch == 0) {
#pragma unroll
            for (int ks = 0; ks < 4; ks++)
#pragma unroll
                for (int mf = 0; mf < 2; mf++) {
                    uint32_t off = (uint32_t)((mf * 16 + (lid & 15)) * SK
                                              + ks * 16 + (lid >> 4) * 8) * 2;
                    ldsm4(smBase + off, aH[ks][mf][0], aH[ks][mf][1],
                                        aH[ks][mf][2], aH[ks][mf][3]);
                }
        }
        const uint32_t kB = smBase + (uint32_t)(QPL + (ch & 1) * KPL) * 2;
#pragma unroll
        for (int ks = 0; ks < 4; ks++) {
            uint32_t bh[2][2];
            uint32_t off = (uint32_t)((wid * 16 + (lid & 7) + (lid >> 4) * 8) * SK
                                      + ks * 16 + ((lid >> 3) & 1) * 8) * 2;
            ldsm4(kB + off, bh[0][0], bh[0][1], bh[1][0], bh[1][1]);
#pragma unroll
            for (int mf = 0; mf < 2; mf++)
#pragma unroll
                for (int nf = 0; nf < 2; nf++)
                    mma16816(acc[mf][ch][nf], aH[ks][mf], bh[nf]);
        }
    }

    // ---- softmax-one ----
    const int rq = lid >> 2, cq = lid & 3;
#pragma unroll
    for (int mf = 0; mf < 2; mf++)
#pragma unroll
        for (int ch = 0; ch < 8; ch++)
#pragma unroll
            for (int nf = 0; nf < 2; nf++)
#pragma unroll
                for (int r = 0; r < 4; r++) acc[mf][ch][nf][r] *= 0.125f;

    float mx[2][2];
#pragma unroll
    for (int mf = 0; mf < 2; mf++)
#pragma unroll
        for (int half = 0; half < 2; half++) {
            float m = -1e30f;
#pragma unroll
            for (int ch = 0; ch < 8; ch++)
#pragma unroll
                for (int nf = 0; nf < 2; nf++)
                    m = fmaxf(m, fmaxf(acc[mf][ch][nf][half*2], acc[mf][ch][nf][half*2+1]));
            m = fmaxf(m, __shfl_xor_sync(0xffffffffu, m, 1));
            m = fmaxf(m, __shfl_xor_sync(0xffffffffu, m, 2));
            mx[mf][half] = m;
        }
    if (cq == 0) {
#pragma unroll
        for (int mf = 0; mf < 2; mf++)
#pragma unroll
            for (int half = 0; half < 2; half++)
                redA[(mf * 16 + half * 8 + rq) * 9 + wid] = mx[mf][half];
    }
    __syncthreads();
#pragma unroll
    for (int mf = 0; mf < 2; mf++)
#pragma unroll
        for (int half = 0; half < 2; half++) {
            float m = -1e30f;
            const float* rr = redA + (mf * 16 + half * 8 + rq) * 9;
#pragma unroll
            for (int w = 0; w < 8; w++) m = fmaxf(m, rr[w]);
            mx[mf][half] = m;
        }

    float sum[2][2] = {{0.f, 0.f}, {0.f, 0.f}};
#pragma unroll
    for (int mf = 0; mf < 2; mf++)
#pragma unroll
        for (int half = 0; half < 2; half++) {
            const float m = mx[mf][half];
            float s = 0.f;
#pragma unroll
            for (int ch = 0; ch < 8; ch++)
#pragma unroll
                for (int nf = 0; nf < 2; nf++) {
                    float e0 = __expf(acc[mf][ch][nf][half*2]     - m);
                    float e1 = __expf(acc[mf][ch][nf][half*2 + 1] - m);
                    acc[mf][ch][nf][half*2]     = e0;
                    acc[mf][ch][nf][half*2 + 1] = e1;
                    s += e0 + e1;
                }
            s += __shfl_xor_sync(0xffffffffu, s, 1);
            s += __shfl_xor_sync(0xffffffffu, s, 2);
            sum[mf][half] = s;
        }
    if (cq == 0) {
#pragma unroll
        for (int mf = 0; mf < 2; mf++)
#pragma unroll
            for (int half = 0; half < 2; half++)
                redB[(mf * 16 + half * 8 + rq) * 9 + wid] = sum[mf][half];
    }
    __syncthreads();
#pragma unroll
    for (int mf = 0; mf < 2; mf++)
#pragma unroll
        for (int half = 0; half < 2; half++) {
            float s = 0.f;
            const float* rr = redB + (mf * 16 + half * 8 + rq) * 9;
#pragma unroll
            for (int w = 0; w < 8; w++) s += rr[w];
            sum[mf][half] = 1.0f / (1.0f + s);
        }

    // ---- write normalized P: fp32 (streaming, output) + fp16 copy for PV ----
#pragma unroll
    for (int mf = 0; mf < 2; mf++)
#pragma unroll
        for (int half = 0; half < 2; half++) {
            const int gr = row0 + mf * 16 + half * 8 + rq;
            const float inv = sum[mf][half];
#pragma unroll
            for (int ch = 0; ch < 8; ch++)
#pragma unroll
                for (int nf = 0; nf < 2; nf++) {
                    const int gc = ch * 128 + wid * 16 + nf * 8 + cq * 2;
                    float p0 = acc[mf][ch][nf][half*2]     * inv;
                    float p1 = acc[mf][ch][nf][half*2 + 1] * inv;
                    __stcs((float2*)(attn + (long)gr * 1024 + gc), make_float2(p0, p1));
                    __half2 ph = __floats2half2_rn(p0, p1);
                    *(uint32_t*)(pOut + (long)gr * 1024 + gc) = *(uint32_t*)&ph;
                }
        }
}

// =====================================================================================
__global__ void cvt_hi(const float* __restrict__ s, __half* __restrict__ hi, int n4)
{
    int i = blockIdx.x * 256 + threadIdx.x;
    if (i >= n4) return;
    float4 v = ((const float4*)s)[i];
    __half h[4] = {__float2half_rn(v.x), __float2half_rn(v.y),
                   __float2half_rn(v.z), __float2half_rn(v.w)};
    ((uint2*)hi)[i] = *(uint2*)h;
}

__global__ void cvt3_hi(const float* __restrict__ a, const float* __restrict__ b,
                        const float* __restrict__ c, __half* __restrict__ o, int n4)
{
    int i = blockIdx.x * 256 + threadIdx.x;
    if (i >= n4) return;
    const float* srcs[3] = {a, b, c};
#pragma unroll
    for (int p = 0; p < 3; p++) {
        float4 v = ((const float4*)srcs[p])[i];
        __half h[4] = {__float2half_rn(v.x), __float2half_rn(v.y),
                       __float2half_rn(v.z), __float2half_rn(v.w)};
        ((uint2*)(o + (long)p * CD))[i] = *(uint2*)h;
    }
}

__global__ void bias_gather(const float* a, const float* b, const float* c, float* o)
{
    const float* src[3] = {a, b, c};
    o[blockIdx.x * 1024 + threadIdx.x] = src[blockIdx.x][threadIdx.x];
}

// =====================================================================================
// channel LayerNorm -> fp16 single planes (up to 3)
// =====================================================================================
__global__ void ln3_kernel(const float* __restrict__ x, int nOut,
    const float* __restrict__ w0, const float* __restrict__ b0,
    const float* __restrict__ w1, const float* __restrict__ b1,
    const float* __restrict__ w2, const float* __restrict__ b2,
    __half* __restrict__ oHi)
{
    const int dx   = threadIdx.x & 31;
    const int lane = threadIdx.x >> 5;
    const int d    = blockIdx.x * 32 + dx;
    const long base = (long)blockIdx.y * CD + d;

    float s = 0.f, ss = 0.f;
    for (int c = lane; c < CC; c += 8) {
        float v = x[base + (long)c * DD];
        s += v; ss += v * v;
    }
    __shared__ float sS[8][33], sQ[8][33];
    sS[lane][dx] = s; sQ[lane][dx] = ss;
    __syncthreads();
    if (lane == 0) {
        float ts = 0.f, tq = 0.f;
        #pragma unroll
        for (int i = 0; i < 8; i++) { ts += sS[i][dx]; tq += sQ[i][dx]; }
        float mean = ts * (1.0f / CC);
        float var  = tq * (1.0f / CC) - mean * mean;
        sS[0][dx] = mean;
        sQ[0][dx] = rsqrtf(var + 1e-6f);
    }
    __syncthreads();
    const float mean = sS[0][dx];
    const float rstd = sQ[0][dx];
    const float* W[3] = {w0, w1, w2};
    const float* Bv[3] = {b0, b1, b2};
    for (int c = lane; c < CC; c += 8) {
        long idx = base + (long)c * DD;
        float xn = (x[idx] - mean) * rstd;
        for (int p = 0; p < nOut; p++)
            oHi[(long)p * BCD + idx] = __float2half_rn(W[p][c] * xn + Bv[p][c]);
    }
}

// =====================================================================================
extern "C" void kernel_launch(void* const* d_in, const int* in_sizes, int n_in,
                              void* d_out, int out_size)
{
    const float* x1      = (const float*)d_in[0];
    const float* lnq_w   = (const float*)d_in[1];
    const float* lnq_b   = (const float*)d_in[2];
    const float* lnk_w   = (const float*)d_in[3];
    const float* lnk_b   = (const float*)d_in[4];
    const float* lnv_w   = (const float*)d_in[5];
    const float* lnv_b   = (const float*)d_in[6];
    const float* wq      = (const float*)d_in[7];
    const float* bq      = (const float*)d_in[8];
    const float* wk      = (const float*)d_in[9];
    const float* bk      = (const float*)d_in[10];
    const float* wv      = (const float*)d_in[11];
    const float* bv      = (const float*)d_in[12];
    const float* ffnln_w = (const float*)d_in[13];
    const float* ffnln_b = (const float*)d_in[14];
    const float* conv1_w = (const float*)d_in[15];
    const float* conv1_b = (const float*)d_in[16];
    const float* conv2_w = (const float*)d_in[17];
    const float* conv2_b = (const float*)d_in[18];

    __half *lnHi, *qkvHi, *wHi;
    __half *c1wHi, *c2wHi, *xlHi, *h1Hi, *pBuf;
    float *xb, *bqkv;
    cudaGetSymbolAddress((void**)&lnHi,  g_ln_hi);
    cudaGetSymbolAddress((void**)&qkvHi, g_qkv_hi);
    cudaGetSymbolAddress((void**)&wHi,   g_w_hi);
    cudaGetSymbolAddress((void**)&c1wHi, g_c1w_hi);
    cudaGetSymbolAddress((void**)&c2wHi, g_c2w_hi);
    cudaGetSymbolAddress((void**)&xlHi,  g_xl_hi);
    cudaGetSymbolAddress((void**)&h1Hi,  g_h1_hi);
    cudaGetSymbolAddress((void**)&pBuf,  g_p);
    cudaGetSymbolAddress((void**)&xb,    g_x);
    cudaGetSymbolAddress((void**)&bqkv,  g_bqkv);

    float* outx = (float*)d_out;
    float* attn = outx + (long)BCD;

    auto kQKV = tc2_gemm<1, 2, false, false, false, true,  false, false, false>;
    auto kPV  = tc2_gemm<1, 0, true,  false, false, false, false, true,  false>;
    auto kC1  = tc2_gemm<1, 2, true,  false, true,  false, true,  false, false>;
    auto kC2  = tc2_gemm<1, 0, true,  false, true,  false, false, true,  false>;
    const int SM_1KB = 2 * (1 * 128 * 40 + 1 * 64 * 40) * 2;  // 30720 (QKV)
    const int SM_1TR = 2 * (1 * 128 * 40 + 1 * 32 * 72) * 2;  // 29696 (PV/C1/C2)
    const int SM_QS  = (32 * 72 + 2 * 128 * 72) * 2 + 2 * 32 * 9 * 4;  // 43776
    cudaFuncSetAttribute(kQKV, cudaFuncAttributeMaxDynamicSharedMemorySize, SM_1KB);
    cudaFuncSetAttribute(kPV,  cudaFuncAttributeMaxDynamicSharedMemorySize, SM_1TR);
    cudaFuncSetAttribute(kC1,  cudaFuncAttributeMaxDynamicSharedMemorySize, SM_1TR);
    cudaFuncSetAttribute(kC2,  cudaFuncAttributeMaxDynamicSharedMemorySize, SM_1TR);
    cudaFuncSetAttribute(qk_softmax, cudaFuncAttributeMaxDynamicSharedMemorySize, SM_QS);

    // launch order keeps launch #5 (ncu -s 5 -c 1) = qk_softmax
    // [0] qkv weight converts (fused)
    cvt3_hi<<<CD / 4 / 256, 256>>>(wq, wk, wv, wHi, CD / 4);
    // [1] biases
    bias_gather<<<3, 1024>>>(bq, bk, bv, bqkv);
    // [2] QKV LayerNorms -> single fp16 planes
    dim3 lng(DD / 32, BB);
    ln3_kernel<<<lng, 256>>>(x1, 3, lnq_w, lnq_b, lnk_w, lnk_b, lnv_w, lnv_b, lnHi);
    // [3] fused QKV linears
    dim3 gqkv(16, 32, 3);
    kQKV<<<gqkv, 128, SM_1KB>>>(lnHi, nullptr, BCD, 1024, wHi, nullptr, 1, CD, 0, 1024,
                                nullptr, qkvHi, nullptr, 1, BCD, 0, 1024,
                                nullptr, bqkv, 1024, 1.f, 4096, 1024, 1024);
    // [4] conv1 weight convert
    cvt_hi<<<4 * CD / 4 / 256, 256>>>(conv1_w, c1wHi, 4 * CD / 4);
    // [5] fused QK softmax-one -> attn (fp32 .cs) + P (fp16)   <- ncu capture
    dim3 gqs(32, BB * HH);
    qk_softmax<<<gqs, 256, SM_QS>>>(qkvHi, qkvHi + BCD, attn, pBuf);
    // [6] O = P V, scatter + x1 residual -> g_x
    dim3 gpv(1, 8, BB * HH);
    kPV<<<gpv, 128, SM_1TR>>>(pBuf, nullptr, 1048576, 1024,
                              qkvHi + 2 * (long)BCD, nullptr, 1, 65536, 0, 64,
                              xb, nullptr, nullptr, 16, CD, 64, 1024,
                              x1, nullptr, 0, 1.f, 1024, 64, 1024);
    // [7] FFN LayerNorm -> xl
    ln3_kernel<<<lng, 256>>>(xb, 1, ffnln_w, ffnln_b, nullptr, nullptr, nullptr, nullptr,
                             xlHi);
    // [8] conv2 weight convert
    cvt_hi<<<4 * CD / 4 / 256, 256>>>(conv2_w, c2wHi, 4 * CD / 4);
    // [9] conv1: h1 = GELU(W1 @ xl_z + b1)
    dim3 gc1(16, 32, BB);
    kC1<<<gc1, 128, SM_1TR>>>(c1wHi, nullptr, 0, 1024, xlHi, nullptr, 1, CD, 0, 1024,
                              nullptr, h1Hi, nullptr, 1, (long)4096 * 1024, 0, 1024,
                              nullptr, conv1_b, 0, 1.f, 4096, 1024, 1024);
    // [10] conv2 + residual
    dim3 gc2(16, 8, BB);
    kC2<<<gc2, 128, SM_1TR>>>(c2wHi, nullptr, 0, 4096, h1Hi, nullptr, 1, (long)4096 * 1024, 0, 1024,
                              outx, nullptr, nullptr, 1, CD, 0, 1024,
                              xb, conv2_b, 0, 1.f, 1024, 1024, 4096);
}

// round 17
// speedup vs baseline: 1.2754x; 1.0141x over previous
#include <cuda_runtime.h>
#include <cuda_fp16.h>
#include <math.h>
#include <stdint.h>

#define BB   4
#define CC   1024
#define DD   1024
#define HH   16
#define CD   (CC*DD)          // 1048576
#define BCD  (BB*CD)          // 4194304
#define H1SZ (BB*4096*1024)   // 16777216

// ---------------- scratch (static __device__ arrays; no runtime alloc) ---------------
__device__ __half g_ln_hi[3*BCD];                  // lnq/lnk/lnv single fp16 planes
__device__ __half g_qkv_hi[3*BCD];                 // q/k/v single fp16 planes
__device__ __half g_w_hi[3*CD];
__device__ __half g_c1w_hi[4*CD];
__device__ __half g_c2w_hi[4*CD];
__device__ __half g_xl_hi[BCD];
__device__ __half g_h1_hi[H1SZ];
__device__ __half g_p[64*1048576];                 // fp16 copy of attn probs
__device__ float g_x[BCD];
__device__ float g_bqkv[3*1024];

// =====================================================================================
// helpers
// =====================================================================================
__device__ __forceinline__ uint32_t smem_u32(const void* p) {
    uint32_t a;
    asm("{ .reg .u64 t; cvta.to.shared.u64 t, %1; cvt.u32.u64 %0, t; }" : "=r"(a) : "l"(p));
    return a;
}
__device__ __forceinline__ void cpa16(uint32_t s, const void* g) {
    asm volatile("cp.async.cg.shared.global [%0], [%1], 16;" :: "r"(s), "l"(g));
}
__device__ __forceinline__ void ldsm4(uint32_t addr, uint32_t& r0, uint32_t& r1,
                                      uint32_t& r2, uint32_t& r3) {
    asm volatile("ldmatrix.sync.aligned.m8n8.x4.shared.b16 {%0,%1,%2,%3}, [%4];"
                 : "=r"(r0), "=r"(r1), "=r"(r2), "=r"(r3) : "r"(addr));
}
__device__ __forceinline__ void ldsm4t(uint32_t addr, uint32_t& r0, uint32_t& r1,
                                       uint32_t& r2, uint32_t& r3) {
    asm volatile("ldmatrix.sync.aligned.m8n8.x4.trans.shared.b16 {%0,%1,%2,%3}, [%4];"
                 : "=r"(r0), "=r"(r1), "=r"(r2), "=r"(r3) : "r"(addr));
}
__device__ __forceinline__ void mma16816(float* c, const uint32_t* a, const uint32_t* b) {
    asm volatile(
        "mma.sync.aligned.m16n8k16.row.col.f32.f16.f16.f32 "
        "{%0,%1,%2,%3}, {%4,%5,%6,%7}, {%8,%9}, {%0,%1,%2,%3};"
        : "+f"(c[0]), "+f"(c[1]), "+f"(c[2]), "+f"(c[3])
        : "r"(a[0]), "r"(a[1]), "r"(a[2]), "r"(a[3]), "r"(b[0]), "r"(b[1]));
}
__device__ __forceinline__ void split1(float v, __half& h, __half& l) {
    h = __float2half_rn(v);
    l = __float2half_rn(v - __half2float(h));
}

// =====================================================================================
// Tensor-core GEMM: block 128x64, 4 warps, BK=32, **3-stage** cp.async ring
// (wait_group 1: two tiles in flight), 4 CTAs/SM.
//   NMMA=1: D = a*b ; NMMA=2: D = (a_hi+a_lo)*b ; NMMA=3: + a_hi*b_lo
//   OMODE: 0 = fp32, 1 = fp16 hi/lo, 2 = fp16 single
// =====================================================================================
template<int NMMA, int OMODE, bool BTRANS, bool ACONV, bool BIAS_M, bool BIAS_N,
         bool GELUF, bool ADDF, bool SCALEF>
__global__ void __launch_bounds__(128, 4)
tc2_gemm(const void* Ahv, const __half* Alo, long strideA, int lda,
         const __half* Bhi, const __half* Blo,
         int bDiv, long bHi, long bLo, int ldb,
         float* Cf, __half* Chi, __half* Clo,
         int cDiv, long cHi, long cLo, int ldc,
         const float* Add, const float* bias, int biasZ,
         float alpha, int M, int N, int K)
{
    constexpr int BN  = 64;
    constexpr int BK  = 32;
    constexpr int SKA = 40;
    constexpr int SN  = BN + 8;
    constexpr int ASZ = 128 * SKA;
    constexpr int BSZ = BTRANS ? (BK * SN) : (BN * SKA);
    constexpr int APL = (NMMA >= 2) ? 2 : 1;
    constexpr int BPL = (NMMA == 3) ? 2 : 1;
    constexpr int STAGE = APL * ASZ + BPL * BSZ;
    constexpr int MF = 4;
    constexpr int NF = 4;

    extern __shared__ __half sm[];

    const int tid = threadIdx.x, wid = tid >> 5, lid = tid & 31;
    const int wm = wid >> 1, wn = wid & 1;
    const int z = blockIdx.z;
    const int row0 = blockIdx.y * 128, col0 = blockIdx.x * BN;

    const __half* Ahi = ACONV ? nullptr : ((const __half*)Ahv + (long)z * strideA);
    const __half* Alz = (ACONV || APL == 1) ? nullptr : (Alo + (long)z * strideA);
    const float* Af = ACONV ? ((const float*)Ahv + (long)z * strideA) : nullptr;
    Bhi += (long)(z / bDiv) * bHi + (long)(z % bDiv) * bLo;
    if (NMMA == 3) Blo += (long)(z / bDiv) * bHi + (long)(z % bDiv) * bLo;
    const long coff = (long)(z / cDiv) * cHi + (long)(z % cDiv) * cLo;
    if (BIAS_N || BIAS_M) bias += (long)z * biasZ;

    const uint32_t smBase = smem_u32(sm);
    const int nIt = K / BK;

    float acc[MF][NF][4];
#pragma unroll
    for (int i = 0; i < MF; i++)
#pragma unroll
        for (int j = 0; j < NF; j++)
#pragma unroll
            for (int r = 0; r < 4; r++) acc[i][j][r] = 0.f;

    float4 av[8];

    auto issueTile = [&](int it, int st) {
        const int k0 = it * BK;
        const uint32_t sbase = smBase + (uint32_t)(st * STAGE) * 2;
        if (!ACONV) {
#pragma unroll
            for (int pl = 0; pl < APL; pl++) {
                const __half* Ag = pl ? Alz : Ahi;
                const uint32_t sd = sbase + (uint32_t)(pl * ASZ) * 2;
#pragma unroll
                for (int i = 0; i < 4; i++) {
                    int idx = tid + (i << 7);
                    int r = idx >> 2, c8 = (idx & 3) << 3;
                    cpa16(sd + (uint32_t)(r * SKA + c8) * 2,
                          Ag + (long)(row0 + r) * lda + k0 + c8);
                }
            }
        }
        if (BTRANS) {
#pragma unroll
            for (int pl = 0; pl < BPL; pl++) {
                const __half* Bg = pl ? Blo : Bhi;
                const uint32_t sd = sbase + (uint32_t)(APL * ASZ + pl * BSZ) * 2;
#pragma unroll
                for (int i = 0; i < 2; i++) {
                    int idx = tid + (i << 7);
                    int k = idx >> 3, c8 = (idx & 7) << 3;
                    cpa16(sd + (uint32_t)(k * SN + c8) * 2,
                          Bg + (long)(k0 + k) * ldb + col0 + c8);
                }
            }
        } else {
#pragma unroll
            for (int pl = 0; pl < BPL; pl++) {
                const __half* Bg = pl ? Blo : Bhi;
                const uint32_t sd = sbase + (uint32_t)(APL * ASZ + pl * BSZ) * 2;
#pragma unroll
                for (int i = 0; i < 2; i++) {
                    int idx = tid + (i << 7);
                    int r = idx >> 2, c8 = (idx & 3) << 3;
                    cpa16(sd + (uint32_t)(r * SKA + c8) * 2,
                          Bg + (long)(col0 + r) * ldb + k0 + c8);
                }
            }
        }
    };
    auto ldgA = [&](int it) {
        const int k0 = it * BK;
#pragma unroll
        for (int i = 0; i < 8; i++) {
            int idx = tid + (i << 7);
            int r = idx >> 3, c4 = (idx & 7) << 2;
            av[i] = *(const float4*)(Af + (long)(row0 + r) * lda + k0 + c4);
        }
    };
    auto stsA = [&](int st) {
        __half* sAhi = sm + st * STAGE;
        __half* sAlo = sAhi + ASZ;
#pragma unroll
        for (int i = 0; i < 8; i++) {
            int idx = tid + (i << 7);
            int r = idx >> 3, c4 = (idx & 7) << 2;
            if (APL == 2) {
                __half h[4], l[4];
                split1(av[i].x, h[0], l[0]); split1(av[i].y, h[1], l[1]);
                split1(av[i].z, h[2], l[2]); split1(av[i].w, h[3], l[3]);
                *(uint2*)(sAhi + r * SKA + c4) = *(uint2*)h;
                *(uint2*)(sAlo + r * SKA + c4) = *(uint2*)l;
            } else {
                __half h[4] = {__float2half_rn(av[i].x), __float2half_rn(av[i].y),
                               __float2half_rn(av[i].z), __float2half_rn(av[i].w)};
                *(uint2*)(sAhi + r * SKA + c4) = *(uint2*)h;
            }
        }
    };

    // prologue: two tiles in flight (no readers yet -> safe)
    if (ACONV) { ldgA(0); stsA(0); }
    issueTile(0, 0);
    asm volatile("cp.async.commit_group;");
    if (nIt > 1) {
        if (ACONV) { ldgA(1); stsA(1); }
        issueTile(1, 1);
    }
    asm volatile("cp.async.commit_group;");

    for (int it = 0; it < nIt; it++) {
        const int s = it % 3;
        // wait for tile it (leave the following group in flight)
        if (it + 1 < nIt) asm volatile("cp.async.wait_group 1;");
        else              asm volatile("cp.async.wait_group 0;");
        __syncthreads();
        // stage (it+2)%3: its readers (iter it-1) retired at this barrier
        if (it + 2 < nIt) {
            if (ACONV) ldgA(it + 2);
            issueTile(it + 2, (it + 2) % 3);
        }
        asm volatile("cp.async.commit_group;");

        const uint32_t base = smBase + (uint32_t)(s * STAGE) * 2;
        const uint32_t aHiB = base, aLoB = base + ASZ * 2;
        const uint32_t bHiB = base + APL * ASZ * 2, bLoB = bHiB + BSZ * 2;

#pragma unroll
        for (int ks = 0; ks < 2; ks++) {
            uint32_t ah[MF][4], al[MF][4], bh[NF][2], bl[NF][2];
#pragma unroll
            for (int mf = 0; mf < MF; mf++) {
                uint32_t off = (uint32_t)((wm * 64 + mf * 16 + (lid & 15)) * SKA
                                          + ks * 16 + (lid >> 4) * 8) * 2;
                ldsm4(aHiB + off, ah[mf][0], ah[mf][1], ah[mf][2], ah[mf][3]);
                if (APL == 2)
                    ldsm4(aLoB + off, al[mf][0], al[mf][1], al[mf][2], al[mf][3]);
            }
            if (BTRANS) {
#pragma unroll
                for (int p = 0; p < NF / 2; p++) {
                    uint32_t off = (uint32_t)((ks * 16 + (lid & 15)) * SN
                                              + wn * 32 + p * 16 + (lid >> 4) * 8) * 2;
                    ldsm4t(bHiB + off, bh[2*p][0], bh[2*p][1], bh[2*p+1][0], bh[2*p+1][1]);
                    if (NMMA == 3)
                        ldsm4t(bLoB + off, bl[2*p][0], bl[2*p][1], bl[2*p+1][0], bl[2*p+1][1]);
                }
            } else {
#pragma unroll
                for (int p = 0; p < NF / 2; p++) {
                    uint32_t off = (uint32_t)((wn * 32 + p * 16 + (lid & 7) + (lid >> 4) * 8) * SKA
                                              + ks * 16 + ((lid >> 3) & 1) * 8) * 2;
                    ldsm4(bHiB + off, bh[2*p][0], bh[2*p][1], bh[2*p+1][0], bh[2*p+1][1]);
                    if (NMMA == 3)
                        ldsm4(bLoB + off, bl[2*p][0], bl[2*p][1], bl[2*p+1][0], bl[2*p+1][1]);
                }
            }
#pragma unroll
            for (int mf = 0; mf < MF; mf++)
#pragma unroll
                for (int nf = 0; nf < NF; nf++)
                    mma16816(acc[mf][nf], ah[mf], bh[nf]);
            if (NMMA == 3) {
#pragma unroll
                for (int mf = 0; mf < MF; mf++)
#pragma unroll
                    for (int nf = 0; nf < NF; nf++)
                        mma16816(acc[mf][nf], ah[mf], bl[nf]);
            }
            if (NMMA >= 2) {
#pragma unroll
                for (int mf = 0; mf < MF; mf++)
#pragma unroll
                    for (int nf = 0; nf < NF; nf++)
                        mma16816(acc[mf][nf], al[mf], bh[nf]);
            }
        }
    }

    // ---- epilogue ----
    float* Cp = (OMODE == 0) ? (Cf + coff) : nullptr;
    __half* ChP = (OMODE != 0) ? (Chi + coff) : nullptr;
    __half* ClP = (OMODE == 1) ? (Clo + coff) : nullptr;
    const float* Ap2 = ADDF ? (Add + coff) : nullptr;
    const int rBase = row0 + wm * 64 + (lid >> 2);
    const int cBase = col0 + wn * 32 + (lid & 3) * 2;
#pragma unroll
    for (int mf = 0; mf < MF; mf++) {
#pragma unroll
        for (int half = 0; half < 2; half++) {
            const int gr = rBase + mf * 16 + half * 8;
            const float bm = BIAS_M ? bias[gr] : 0.f;
#pragma unroll
            for (int nf = 0; nf < NF; nf++) {
                const int gc = cBase + nf * 8;
                float v0 = acc[mf][nf][half * 2 + 0];
                float v1 = acc[mf][nf][half * 2 + 1];
                if (SCALEF) { v0 *= alpha; v1 *= alpha; }
                if (BIAS_M) { v0 += bm; v1 += bm; }
                if (BIAS_N) { v0 += bias[gc]; v1 += bias[gc + 1]; }
                if (GELUF) {
                    v0 = 0.5f * v0 * (1.0f + erff(v0 * 0.70710678118654752f));
                    v1 = 0.5f * v1 * (1.0f + erff(v1 * 0.70710678118654752f));
                }
                long off = (long)gr * ldc + gc;
                if (ADDF) { v0 += Ap2[off]; v1 += Ap2[off + 1]; }
                if (OMODE == 1) {
                    __half h0, l0, h1, l1;
                    split1(v0, h0, l0); split1(v1, h1, l1);
                    __half hp[2] = {h0, h1}, lp[2] = {l0, l1};
                    *(uint32_t*)(ChP + off) = *(uint32_t*)hp;
                    *(uint32_t*)(ClP + off) = *(uint32_t*)lp;
                } else if (OMODE == 2) {
                    __half hp[2] = {__float2half_rn(v0), __float2half_rn(v1)};
                    *(uint32_t*)(ChP + off) = *(uint32_t*)hp;
                } else {
                    *(float2*)(Cp + off) = make_float2(v0, v1);
                }
            }
        }
    }
}

// =====================================================================================
// Fused QK^T * 0.125 + softmax-one. fp32 attn (streaming) + fp16 P copy. 1-MMA.
// =====================================================================================
__global__ void __launch_bounds__(256, 1)
qk_softmax(const __half* __restrict__ qH, const __half* __restrict__ kH,
           float* __restrict__ attn, __half* __restrict__ pOut)
{
    constexpr int SK = 72;
    constexpr int QPL = 32 * SK;
    constexpr int KPL = 128 * SK;
    extern __shared__ __half sm[];
    float* redA = (float*)(sm + QPL + 2 * KPL);
    float* redB = redA + 32 * 9;

    const int tid = threadIdx.x, wid = tid >> 5, lid = tid & 31;
    const int z = blockIdx.y;
    const int row0 = blockIdx.x * 32;
    const __half* Qh = qH + (long)z * 65536;
    const __half* Kh = kH + (long)z * 65536;
    attn += (long)z * 1048576;
    pOut += (long)z * 1048576;

    const uint32_t smBase = smem_u32(sm);

    {
        int r = tid >> 3, c8 = (tid & 7) << 3;
        cpa16(smBase + (uint32_t)(r * SK + c8) * 2, Qh + (long)(row0 + r) * 64 + c8);
    }
    auto issueK = [&](int ch, int st) {
        const uint32_t sd = smBase + (uint32_t)(QPL + st * KPL) * 2;
#pragma unroll
        for (int i = 0; i < 4; i++) {
            int idx = tid + (i << 8);
            int r = idx >> 3, c8 = (idx & 7) << 3;
            cpa16(sd + (uint32_t)(r * SK + c8) * 2,
                  Kh + (long)(ch * 128 + r) * 64 + c8);
        }
    };
    issueK(0, 0);
    asm volatile("cp.async.commit_group;");

    float acc[2][8][2][4];
#pragma unroll
    for (int mf = 0; mf < 2; mf++)
#pragma unroll
        for (int ch = 0; ch < 8; ch++)
#pragma unroll
            for (int nf = 0; nf < 2; nf++)
#pragma unroll
                for (int r = 0; r < 4; r++) acc[mf][ch][nf][r] = 0.f;

    uint32_t aH[4][2][4];

    for (int ch = 0; ch < 8; ch++) {
        asm volatile("cp.async.wait_group 0;");
        __syncthreads();
        if (ch + 1 < 8) {
            issueK(ch + 1, (ch + 1) & 1);
            asm volatile("cp.async.commit_group;");
        }
        if (ch == 0) {
#pragma unroll
            for (int ks = 0; ks < 4; ks++)
#pragma unroll
                for (int mf = 0; mf < 2; mf++) {
                    uint32_t off = (uint32_t)((mf * 16 + (lid & 15)) * SK
                                              + ks * 16 + (lid >> 4) * 8) * 2;
                    ldsm4(smBase + off, aH[ks][mf][0], aH[ks][mf][1],
                                        aH[ks][mf][2], aH[ks][mf][3]);
                }
        }
        const uint32_t kB = smBase + (uint32_t)(QPL + (ch & 1) * KPL) * 2;
#pragma unroll
        for (int ks = 0; ks < 4; ks++) {
            uint32_t bh[2][2];
            uint32_t off = (uint32_t)((wid * 16 + (lid & 7) + (lid >> 4) * 8) * SK
                                      + ks * 16 + ((lid >> 3) & 1) * 8) * 2;
            ldsm4(kB + off, bh[0][0], bh[0][1], bh[1][0], bh[1][1]);
#pragma unroll
            for (int mf = 0; mf < 2; mf++)
#pragma unroll
                for (int nf = 0; nf < 2; nf++)
                    mma16816(acc[mf][ch][nf], aH[ks][mf], bh[nf]);
        }
    }

    // ---- softmax-one ----
    const int rq = lid >> 2, cq = lid & 3;
#pragma unroll
    for (int mf = 0; mf < 2; mf++)
#pragma unroll
        for (int ch = 0; ch < 8; ch++)
#pragma unroll
            for (int nf = 0; nf < 2; nf++)
#pragma unroll
                for (int r = 0; r < 4; r++) acc[mf][ch][nf][r] *= 0.125f;

    float mx[2][2];
#pragma unroll
    for (int mf = 0; mf < 2; mf++)
#pragma unroll
        for (int half = 0; half < 2; half++) {
            float m = -1e30f;
#pragma unroll
            for (int ch = 0; ch < 8; ch++)
#pragma unroll
                for (int nf = 0; nf < 2; nf++)
                    m = fmaxf(m, fmaxf(acc[mf][ch][nf][half*2], acc[mf][ch][nf][half*2+1]));
            m = fmaxf(m, __shfl_xor_sync(0xffffffffu, m, 1));
            m = fmaxf(m, __shfl_xor_sync(0xffffffffu, m, 2));
            mx[mf][half] = m;
        }
    if (cq == 0) {
#pragma unroll
        for (int mf = 0; mf < 2; mf++)
#pragma unroll
            for (int half = 0; half < 2; half++)
                redA[(mf * 16 + half * 8 + rq) * 9 + wid] = mx[mf][half];
    }
    __syncthreads();
#pragma unroll
    for (int mf = 0; mf < 2; mf++)
#pragma unroll
        for (int half = 0; half < 2; half++) {
            float m = -1e30f;
            const float* rr = redA + (mf * 16 + half * 8 + rq) * 9;
#pragma unroll
            for (int w = 0; w < 8; w++) m = fmaxf(m, rr[w]);
            mx[mf][half] = m;
        }

    float sum[2][2] = {{0.f, 0.f}, {0.f, 0.f}};
#pragma unroll
    for (int mf = 0; mf < 2; mf++)
#pragma unroll
        for (int half = 0; half < 2; half++) {
            const float m = mx[mf][half];
            float s = 0.f;
#pragma unroll
            for (int ch = 0; ch < 8; ch++)
#pragma unroll
                for (int nf = 0; nf < 2; nf++) {
                    float e0 = __expf(acc[mf][ch][nf][half*2]     - m);
                    float e1 = __expf(acc[mf][ch][nf][half*2 + 1] - m);
                    acc[mf][ch][nf][half*2]     = e0;
                    acc[mf][ch][nf][half*2 + 1] = e1;
                    s += e0 + e1;
                }
            s += __shfl_xor_sync(0xffffffffu, s, 1);
            s += __shfl_xor_sync(0xffffffffu, s, 2);
            sum[mf][half] = s;
        }
    if (cq == 0) {
#pragma unroll
        for (int mf = 0; mf < 2; mf++)
#pragma unroll
            for (int half = 0; half < 2; half++)
                redB[(mf * 16 + half * 8 + rq) * 9 + wid] = sum[mf][half];
    }
    __syncthreads();
#pragma unroll
    for (int mf = 0; mf < 2; mf++)
#pragma unroll
        for (int half = 0; half < 2; half++) {
            float s = 0.f;
            const float* rr = redB + (mf * 16 + half * 8 + rq) * 9;
#pragma unroll
            for (int w = 0; w < 8; w++) s += rr[w];
            sum[mf][half] = 1.0f / (1.0f + s);
        }

#pragma unroll
    for (int mf = 0; mf < 2; mf++)
#pragma unroll
        for (int half = 0; half < 2; half++) {
            const int gr = row0 + mf * 16 + half * 8 + rq;
            const float inv = sum[mf][half];
#pragma unroll
            for (int ch = 0; ch < 8; ch++)
#pragma unroll
                for (int nf = 0; nf < 2; nf++) {
                    const int gc = ch * 128 + wid * 16 + nf * 8 + cq * 2;
                    float p0 = acc[mf][ch][nf][half*2]     * inv;
                    float p1 = acc[mf][ch][nf][half*2 + 1] * inv;
                    __stcs((float2*)(attn + (long)gr * 1024 + gc), make_float2(p0, p1));
                    __half2 ph = __floats2half2_rn(p0, p1);
                    *(uint32_t*)(pOut + (long)gr * 1024 + gc) = *(uint32_t*)&ph;
                }
        }
}

// =====================================================================================
__global__ void cvt_hi(const float* __restrict__ s, __half* __restrict__ hi, int n4)
{
    int i = blockIdx.x * 256 + threadIdx.x;
    if (i >= n4) return;
    float4 v = ((const float4*)s)[i];
    __half h[4] = {__float2half_rn(v.x), __float2half_rn(v.y),
                   __float2half_rn(v.z), __float2half_rn(v.w)};
    ((uint2*)hi)[i] = *(uint2*)h;
}

__global__ void cvt3_hi(const float* __restrict__ a, const float* __restrict__ b,
                        const float* __restrict__ c, __half* __restrict__ o, int n4)
{
    int i = blockIdx.x * 256 + threadIdx.x;
    if (i >= n4) return;
    const float* srcs[3] = {a, b, c};
#pragma unroll
    for (int p = 0; p < 3; p++) {
        float4 v = ((const float4*)srcs[p])[i];
        __half h[4] = {__float2half_rn(v.x), __float2half_rn(v.y),
                       __float2half_rn(v.z), __float2half_rn(v.w)};
        ((uint2*)(o + (long)p * CD))[i] = *(uint2*)h;
    }
}

__global__ void bias_gather(const float* a, const float* b, const float* c, float* o)
{
    const float* src[3] = {a, b, c};
    o[blockIdx.x * 1024 + threadIdx.x] = src[blockIdx.x][threadIdx.x];
}

// =====================================================================================
// channel LayerNorm -> fp16 single planes (up to 3)
// =====================================================================================
__global__ void ln3_kernel(const float* __restrict__ x, int nOut,
    const float* __restrict__ w0, const float* __restrict__ b0,
    const float* __restrict__ w1, const float* __restrict__ b1,
    const float* __restrict__ w2, const float* __restrict__ b2,
    __half* __restrict__ oHi)
{
    const int dx   = threadIdx.x & 31;
    const int lane = threadIdx.x >> 5;
    const int d    = blockIdx.x * 32 + dx;
    const long base = (long)blockIdx.y * CD + d;

    float s = 0.f, ss = 0.f;
    for (int c = lane; c < CC; c += 8) {
        float v = x[base + (long)c * DD];
        s += v; ss += v * v;
    }
    __shared__ float sS[8][33], sQ[8][33];
    sS[lane][dx] = s; sQ[lane][dx] = ss;
    __syncthreads();
    if (lane == 0) {
        float ts = 0.f, tq = 0.f;
        #pragma unroll
        for (int i = 0; i < 8; i++) { ts += sS[i][dx]; tq += sQ[i][dx]; }
        float mean = ts * (1.0f / CC);
        float var  = tq * (1.0f / CC) - mean * mean;
        sS[0][dx] = mean;
        sQ[0][dx] = rsqrtf(var + 1e-6f);
    }
    __syncthreads();
    const float mean = sS[0][dx];
    const float rstd = sQ[0][dx];
    const float* W[3] = {w0, w1, w2};
    const float* Bv[3] = {b0, b1, b2};
    for (int c = lane; c < CC; c += 8) {
        long idx = base + (long)c * DD;
        float xn = (x[idx] - mean) * rstd;
        for (int p = 0; p < nOut; p++)
            oHi[(long)p * BCD + idx] = __float2half_rn(W[p][c] * xn + Bv[p][c]);
    }
}

// =====================================================================================
extern "C" void kernel_launch(void* const* d_in, const int* in_sizes, int n_in,
                              void* d_out, int out_size)
{
    const float* x1      = (const float*)d_in[0];
    const float* lnq_w   = (const float*)d_in[1];
    const float* lnq_b   = (const float*)d_in[2];
    const float* lnk_w   = (const float*)d_in[3];
    const float* lnk_b   = (const float*)d_in[4];
    const float* lnv_w   = (const float*)d_in[5];
    const float* lnv_b   = (const float*)d_in[6];
    const float* wq      = (const float*)d_in[7];
    const float* bq      = (const float*)d_in[8];
    const float* wk      = (const float*)d_in[9];
    const float* bk      = (const float*)d_in[10];
    const float* wv      = (const float*)d_in[11];
    const float* bv      = (const float*)d_in[12];
    const float* ffnln_w = (const float*)d_in[13];
    const float* ffnln_b = (const float*)d_in[14];
    const float* conv1_w = (const float*)d_in[15];
    const float* conv1_b = (const float*)d_in[16];
    const float* conv2_w = (const float*)d_in[17];
    const float* conv2_b = (const float*)d_in[18];

    __half *lnHi, *qkvHi, *wHi;
    __half *c1wHi, *c2wHi, *xlHi, *h1Hi, *pBuf;
    float *xb, *bqkv;
    cudaGetSymbolAddress((void**)&lnHi,  g_ln_hi);
    cudaGetSymbolAddress((void**)&qkvHi, g_qkv_hi);
    cudaGetSymbolAddress((void**)&wHi,   g_w_hi);
    cudaGetSymbolAddress((void**)&c1wHi, g_c1w_hi);
    cudaGetSymbolAddress((void**)&c2wHi, g_c2w_hi);
    cudaGetSymbolAddress((void**)&xlHi,  g_xl_hi);
    cudaGetSymbolAddress((void**)&h1Hi,  g_h1_hi);
    cudaGetSymbolAddress((void**)&pBuf,  g_p);
    cudaGetSymbolAddress((void**)&xb,    g_x);
    cudaGetSymbolAddress((void**)&bqkv,  g_bqkv);

    float* outx = (float*)d_out;
    float* attn = outx + (long)BCD;

    auto kQKV = tc2_gemm<1, 2, false, false, false, true,  false, false, false>;
    auto kPV  = tc2_gemm<1, 0, true,  false, false, false, false, true,  false>;
    auto kC1  = tc2_gemm<1, 2, true,  false, true,  false, true,  false, false>;
    auto kC2  = tc2_gemm<1, 0, true,  false, true,  false, false, true,  false>;
    // 3-stage rings
    const int SM_1KB = 3 * (1 * 128 * 40 + 1 * 64 * 40) * 2;  // 46080 (QKV)
    const int SM_1TR = 3 * (1 * 128 * 40 + 1 * 32 * 72) * 2;  // 44544 (PV/C1/C2)
    const int SM_QS  = (32 * 72 + 2 * 128 * 72) * 2 + 2 * 32 * 9 * 4;  // 43776
    cudaFuncSetAttribute(kQKV, cudaFuncAttributeMaxDynamicSharedMemorySize, SM_1KB);
    cudaFuncSetAttribute(kPV,  cudaFuncAttributeMaxDynamicSharedMemorySize, SM_1TR);
    cudaFuncSetAttribute(kC1,  cudaFuncAttributeMaxDynamicSharedMemorySize, SM_1TR);
    cudaFuncSetAttribute(kC2,  cudaFuncAttributeMaxDynamicSharedMemorySize, SM_1TR);
    cudaFuncSetAttribute(qk_softmax, cudaFuncAttributeMaxDynamicSharedMemorySize, SM_QS);

    // launch order keeps launch #5 (ncu -s 5 -c 1) = qk_softmax
    cvt3_hi<<<CD / 4 / 256, 256>>>(wq, wk, wv, wHi, CD / 4);
    bias_gather<<<3, 1024>>>(bq, bk, bv, bqkv);
    dim3 lng(DD / 32, BB);
    ln3_kernel<<<lng, 256>>>(x1, 3, lnq_w, lnq_b, lnk_w, lnk_b, lnv_w, lnv_b, lnHi);
    dim3 gqkv(16, 32, 3);
    kQKV<<<gqkv, 128, SM_1KB>>>(lnHi, nullptr, BCD, 1024, wHi, nullptr, 1, CD, 0, 1024,
                                nullptr, qkvHi, nullptr, 1, BCD, 0, 1024,
                                nullptr, bqkv, 1024, 1.f, 4096, 1024, 1024);
    cvt_hi<<<4 * CD / 4 / 256, 256>>>(conv1_w, c1wHi, 4 * CD / 4);
    dim3 gqs(32, BB * HH);
    qk_softmax<<<gqs, 256, SM_QS>>>(qkvHi, qkvHi + BCD, attn, pBuf);
    dim3 gpv(1, 8, BB * HH);
    kPV<<<gpv, 128, SM_1TR>>>(pBuf, nullptr, 1048576, 1024,
                              qkvHi + 2 * (long)BCD, nullptr, 1, 65536, 0, 64,
                              xb, nullptr, nullptr, 16, CD, 64, 1024,
                              x1, nullptr, 0, 1.f, 1024, 64, 1024);
    ln3_kernel<<<lng, 256>>>(xb, 1, ffnln_w, ffnln_b, nullptr, nullptr, nullptr, nullptr,
                             xlHi);
    cvt_hi<<<4 * CD / 4 / 256, 256>>>(conv2_w, c2wHi, 4 * CD / 4);
    dim3 gc1(16, 32, BB);
    kC1<<<gc1, 128, SM_1TR>>>(c1wHi, nullptr, 0, 1024, xlHi, nullptr, 1, CD, 0, 1024,
                              nullptr, h1Hi, nullptr, 1, (long)4096 * 1024, 0, 1024,
                              nullptr, conv1_b, 0, 1.f, 4096, 1024, 1024);
    dim3 gc2(16, 8, BB);
    kC2<<<gc2, 128, SM_1TR>>>(c2wHi, nullptr, 0, 4096, h1Hi, nullptr, 1, (long)4096 * 1024, 0, 1024,
                              outx, nullptr, nullptr, 1, CD, 0, 1024,
                              xb, conv2_b, 0, 1.f, 1024, 1024, 4096);
}